// round 11
// baseline (speedup 1.0000x reference)
#include <cuda_runtime.h>
#include <math.h>
#include <stdint.h>

// Problem constants
#define B_ 8
#define N_ 1024
#define E_ 128

typedef unsigned long long ull;

// ---------------- packed f32x2 helpers (sm_103a FFMA2 path) ----------------
__device__ __forceinline__ ull bcast2(float a) {
    ull r; asm("mov.b64 %0, {%1, %1};" : "=l"(r) : "f"(a)); return r;
}
__device__ __forceinline__ void fma2(ull& d, ull a, ull b) {
    asm("fma.rn.f32x2 %0, %1, %2, %0;" : "+l"(d) : "l"(a), "l"(b));
}
__device__ __forceinline__ void unpack2(ull v, float& lo, float& hi) {
    asm("mov.b64 {%0, %1}, %2;" : "=f"(lo), "=f"(hi) : "l"(v));
}
__device__ __forceinline__ void lds2x2(ull& a, ull& b, uint32_t addr) {
    asm volatile("ld.shared.v2.b64 {%0, %1}, [%2];"
                 : "=l"(a), "=l"(b) : "r"(addr));
}
__device__ __forceinline__ uint32_t saddr(const void* p) {
    return (uint32_t)__cvta_generic_to_shared(p);
}

// ---------------- tf32 mma helpers ----------------------------------------
__device__ __forceinline__ float f2tf32(float x) {
    uint32_t r; asm("cvt.rna.tf32.f32 %0, %1;" : "=r"(r) : "f"(x));
    return __uint_as_float(r);
}
__device__ __forceinline__ void mma_tf32(float* d, const uint32_t* a,
                                         const uint32_t* b) {
    asm volatile(
        "mma.sync.aligned.m16n8k8.row.col.f32.tf32.tf32.f32 "
        "{%0,%1,%2,%3}, {%4,%5,%6,%7}, {%8,%9}, {%0,%1,%2,%3};\n"
        : "+f"(d[0]), "+f"(d[1]), "+f"(d[2]), "+f"(d[3])
        : "r"(a[0]), "r"(a[1]), "r"(a[2]), "r"(a[3]), "r"(b[0]), "r"(b[1]));
}

// ---------------- cp.async helpers -----------------------------------------
__device__ __forceinline__ void cpa16(uint32_t dst, const void* src) {
    asm volatile("cp.async.cg.shared.global [%0], [%1], 16;"
                 :: "r"(dst), "l"(src));
}
__device__ __forceinline__ void cp_commit() {
    asm volatile("cp.async.commit_group;");
}
__device__ __forceinline__ void cp_wait1() {
    asm volatile("cp.async.wait_group 1;");
}
__device__ __forceinline__ void cp_wait0() {
    asm volatile("cp.async.wait_group 0;");
}

// C-frag (c0,c1 at cols 2t,2t+1) -> A-frag (col t) relayout + rna cvt
__device__ __forceinline__ uint32_t relay(float c0, float c1, int src, bool odd) {
    float x = __shfl_sync(0xffffffffu, c0, src);
    float y = __shfl_sync(0xffffffffu, c1, src);
    uint32_t r;
    asm("cvt.rna.tf32.f32 %0, %1;" : "=r"(r) : "f"(odd ? y : x));
    return r;
}

// ---------------- scratch (static device globals; no allocation) ----------
__device__ float g_Hp[B_ * N_ * E_];            // 4 MB
__device__ float g_Hpr[B_ * N_ * E_];           // 4 MB (rna tf32 copy)
__device__ float g_qkv[B_ * N_ * 3 * E_];       // 12 MB
__device__ float g_attn[(size_t)B_ * N_ * N_];  // 32 MB (unnormalized exp)
__device__ float g_rowsum[B_ * N_];             // 32 KB
__device__ float g_oA[B_ * N_ * E_];            // split-K partials
__device__ float g_oB[B_ * N_ * E_];
__device__ float g_lA[B_ * N_ * 8];
__device__ float g_lB[B_ * N_ * 8];
__device__ float g_o[B_ * N_ * E_];             // combined MHA output
__device__ float g_o2[B_ * N_ * E_];            // out-proj output

// ---------------------------------------------------------------------------
// rna tf32 rounding pass: dst[i] = tf32(src[i])  (may be in-place)
// ---------------------------------------------------------------------------
__global__ __launch_bounds__(256) void round_tf32(
    const float* __restrict__ src, float* __restrict__ dst)
{
    int i = blockIdx.x * 256 + threadIdx.x;
    float4 v = ((const float4*)src)[i];
    v.x = f2tf32(v.x); v.y = f2tf32(v.y);
    v.z = f2tf32(v.z); v.w = f2tf32(v.w);
    ((float4*)dst)[i] = v;
}

// ---------------------------------------------------------------------------
// Generic GEMM + bias (scalar FFMA2, kept fp32 for precision headroom)
// ---------------------------------------------------------------------------
__global__ __launch_bounds__(256) void gemm_bias(
    const float* __restrict__ A, const float* __restrict__ W,
    const float* __restrict__ bias, float* __restrict__ C, int NC)
{
    __shared__ float As[32][68];
    __shared__ float Ws[32][132];

    int row0 = blockIdx.x * 64;
    int col0 = blockIdx.y * 128;
    int tid  = threadIdx.x;
    int tx   = tid & 15;
    int ty   = tid >> 4;

    ull acc2[4][4] = {};
    uint32_t wb = saddr(&Ws[0][tx * 8]);

    for (int k0 = 0; k0 < 128; k0 += 32) {
        #pragma unroll
        for (int i = 0; i < 2; i++) {
            int idx = tid + i * 256;
            int r   = idx >> 3;
            int kk  = (idx & 7) << 2;
            float4 v = *(const float4*)&A[(size_t)(row0 + r) * 128 + k0 + kk];
            As[kk + 0][r] = v.x; As[kk + 1][r] = v.y;
            As[kk + 2][r] = v.z; As[kk + 3][r] = v.w;
        }
        #pragma unroll
        for (int i = 0; i < 4; i++) {
            int idx = tid + i * 256;
            int kk  = idx >> 5;
            int c   = (idx & 31) << 2;
            *(float4*)&Ws[kk][c] =
                *(const float4*)&W[(size_t)(k0 + kk) * NC + col0 + c];
        }
        __syncthreads();

        #pragma unroll
        for (int kk = 0; kk < 32; kk++) {
            float a[4];
            *(float4*)&a[0] = *(const float4*)&As[kk][ty * 4];
            ull b2[4];
            lds2x2(b2[0], b2[1], wb + kk * 528);
            lds2x2(b2[2], b2[3], wb + kk * 528 + 16);
            #pragma unroll
            for (int i = 0; i < 4; i++) {
                ull av = bcast2(a[i]);
                #pragma unroll
                for (int j = 0; j < 4; j++) fma2(acc2[i][j], av, b2[j]);
            }
        }
        __syncthreads();
    }

    float bv[8];
    #pragma unroll
    for (int j = 0; j < 8; j++) bv[j] = bias[col0 + tx * 8 + j];

    #pragma unroll
    for (int i = 0; i < 4; i++) {
        float s[8];
        #pragma unroll
        for (int j = 0; j < 4; j++) unpack2(acc2[i][j], s[2 * j], s[2 * j + 1]);
        size_t off = (size_t)(row0 + ty * 4 + i) * NC + col0 + tx * 8;
        float4 o0, o1;
        o0.x = s[0] + bv[0]; o0.y = s[1] + bv[1];
        o0.z = s[2] + bv[2]; o0.w = s[3] + bv[3];
        o1.x = s[4] + bv[4]; o1.y = s[5] + bv[5];
        o1.z = s[6] + bv[6]; o1.w = s[7] + bv[7];
        *(float4*)&C[off]     = o0;
        *(float4*)&C[off + 4] = o1;
    }
}

// ---------------------------------------------------------------------------
// Tensor-core gated scores + fused exp + row-sum, cp.async double-buffered.
// Inputs pre-rounded to tf32 (Hpr) so raw cp.async staging is lossless.
// Block tile 128(n) x 64(m); 8 warps = 2(n) x 4(m). grid = (8, 16, 8).
// ---------------------------------------------------------------------------
struct GatedSmem {
    float Ns[2][128][36];
    float Ms[2][64][36];
};

__device__ __forceinline__ void gated_issue(
    GatedSmem& S, int bi, const float* Hb, int n0, int m0, int k0, int t)
{
    #pragma unroll
    for (int i = 0; i < 4; i++) {
        int idx = t + i * 256;
        int r = idx >> 3, kk = (idx & 7) << 2;
        cpa16(saddr(&S.Ns[bi][r][kk]), &Hb[(size_t)(n0 + r) * 128 + k0 + kk]);
    }
    #pragma unroll
    for (int i = 0; i < 2; i++) {
        int idx = t + i * 256;
        int r = idx >> 3, kk = (idx & 7) << 2;
        cpa16(saddr(&S.Ms[bi][r][kk]), &Hb[(size_t)(m0 + r) * 128 + k0 + kk]);
    }
}

__global__ __launch_bounds__(256, 3) void gated_tc(
    const float* __restrict__ Hpr, const float* __restrict__ Adj,
    float* __restrict__ out, float* __restrict__ rowsum)
{
    extern __shared__ char gs_raw[];
    GatedSmem& S = *reinterpret_cast<GatedSmem*>(gs_raw);

    int b  = blockIdx.z;
    int n0 = blockIdx.x * 128;
    int m0 = blockIdx.y * 64;
    const float* Hb = Hpr + (size_t)b * N_ * E_;

    int t    = threadIdx.x;
    int w    = t >> 5;
    int lane = t & 31;
    int g    = lane >> 2;
    int tig  = lane & 3;
    int wn   = (w & 1) * 64;
    int wm   = (w >> 1) * 16;

    gated_issue(S, 0, Hb, n0, m0, 0, t);  cp_commit();
    gated_issue(S, 1, Hb, n0, m0, 32, t); cp_commit();

    float acc[4][2][4] = {};

    #pragma unroll 1
    for (int c = 0; c < 4; c++) {
        int bi = c & 1;
        if (c < 3) cp_wait1(); else cp_wait0();
        __syncthreads();

        #pragma unroll
        for (int s = 0; s < 4; s++) {
            uint32_t af[4][4], bf[2][2];
            #pragma unroll
            for (int mt = 0; mt < 4; mt++) {
                const float* base = &S.Ns[bi][wn + 16 * mt + g][8 * s + tig];
                af[mt][0] = __float_as_uint(base[0]);
                af[mt][1] = __float_as_uint(base[8 * 36]);
                af[mt][2] = __float_as_uint(base[4]);
                af[mt][3] = __float_as_uint(base[8 * 36 + 4]);
            }
            #pragma unroll
            for (int nt = 0; nt < 2; nt++) {
                const float* base = &S.Ms[bi][wm + 8 * nt + g][8 * s + tig];
                bf[nt][0] = __float_as_uint(base[0]);
                bf[nt][1] = __float_as_uint(base[4]);
            }
            #pragma unroll
            for (int mt = 0; mt < 4; mt++)
                #pragma unroll
                for (int nt = 0; nt < 2; nt++)
                    mma_tf32(acc[mt][nt], af[mt], bf[nt]);
        }

        __syncthreads();
        if (c + 2 < 4) {
            gated_issue(S, bi, Hb, n0, m0, (c + 2) * 32, t);
            cp_commit();
        }
    }

    // epilogue: leaky -> *Adj -> exp -> store + rowsum atomics
    #pragma unroll
    for (int mt = 0; mt < 4; mt++) {
        #pragma unroll
        for (int eh = 0; eh < 2; eh++) {
            int n = n0 + wn + 16 * mt + g + eh * 8;
            float partial = 0.f;
            #pragma unroll
            for (int nt = 0; nt < 2; nt++) {
                int m = m0 + wm + 8 * nt + 2 * tig;
                size_t addr = ((size_t)b * N_ + n) * N_ + m;
                float2 adj = *(const float2*)&Adj[addr];
                float v0 = acc[mt][nt][2 * eh];
                float v1 = acc[mt][nt][2 * eh + 1];
                v0 = (v0 >= 0.f) ? v0 : 0.2f * v0;
                v1 = (v1 >= 0.f) ? v1 : 0.2f * v1;
                float e0 = __expf(v0 * adj.x);
                float e1 = __expf(v1 * adj.y);
                partial += e0 + e1;
                *(float2*)&out[addr] = make_float2(e0, e1);
            }
            partial += __shfl_xor_sync(0xffffffffu, partial, 1);
            partial += __shfl_xor_sync(0xffffffffu, partial, 2);
            if (tig == 0)
                atomicAdd(&rowsum[(size_t)b * N_ + n], partial);
        }
    }
}

// ---------------------------------------------------------------------------
// Tensor-core fused MHA, split-K(2), shuffle P-relayout (no P smem tile).
// Block = 32 queries x 8 heads (warp = head); grid = (N/32, B, 2).
// Writes UNNORMALIZED partial output + partial row-sums.
// ---------------------------------------------------------------------------
struct MhaSmem {
    float Ks[2][32][132];
    float Vs[2][32][132];
    float Wm[2][32][36];
};

__device__ __forceinline__ void mha_issue(
    MhaSmem& S, int bi, const float* kvbase, const float* mbase,
    int m0, int t)
{
    int srow = t >> 3;
    int sc16 = (t & 7) * 16;
    int mc4  = (t & 7) * 4;
    const float* kr = kvbase + (size_t)(m0 + srow) * 384 + 128 + sc16;
    uint32_t kd = saddr(&S.Ks[bi][srow][sc16]);
    uint32_t vd = saddr(&S.Vs[bi][srow][sc16]);
    #pragma unroll
    for (int c = 0; c < 16; c += 4) {
        cpa16(kd + c * 4, kr + c);
        cpa16(vd + c * 4, kr + 128 + c);
    }
    cpa16(saddr(&S.Wm[bi][srow][mc4]),
          mbase + (size_t)srow * N_ + m0 + mc4);
}

__global__ void __launch_bounds__(256, 3) mha_tc(
    const float* __restrict__ qkv, const float* __restrict__ attn,
    const float* __restrict__ rowsum,
    float* __restrict__ OA, float* __restrict__ OB,
    float* __restrict__ LA, float* __restrict__ LB)
{
    extern __shared__ char smem_raw[];
    MhaSmem& S = *reinterpret_cast<MhaSmem*>(smem_raw);

    int b    = blockIdx.y;
    int n0   = blockIdx.x * 32;
    int msta = blockIdx.z * 512;
    int t    = threadIdx.x;
    int h    = t >> 5;
    int lane = t & 31;
    int g    = lane >> 2;
    int tig  = lane & 3;
    int src0 = (lane & 28) | (tig >> 1);
    int src1 = src0 + 2;
    bool odd = tig & 1;

    float* Op = blockIdx.z ? OB : OA;
    float* Lp = blockIdx.z ? LB : LA;

    const float* kvbase = qkv + (size_t)b * N_ * 384;
    const float* mbase  = attn + ((size_t)b * N_ + n0) * N_;

    mha_issue(S, 0, kvbase, mbase, msta, t);      cp_commit();
    mha_issue(S, 1, kvbase, mbase, msta + 32, t); cp_commit();

    const float* rsb = rowsum + (size_t)b * N_ + n0;
    float is0 = 1.0f / rsb[g];
    float is1 = 1.0f / rsb[g + 8];
    float is2 = 1.0f / rsb[g + 16];
    float is3 = 1.0f / rsb[g + 24];

    // Q fragments (pre-rounded qkv; *0.25 exact; rna cvt is identity-safe)
    uint32_t qf[2][2][4];
    {
        const float* qbase = qkv + ((size_t)b * N_ + n0) * 384 + h * 16;
        #pragma unroll
        for (int i = 0; i < 2; i++)
            #pragma unroll
            for (int s = 0; s < 2; s++) {
                const float* p0 = qbase + (size_t)(16 * i + g) * 384 + 8 * s + tig;
                const float* p1 = p0 + 8 * 384;
                qf[i][s][0] = __float_as_uint(f2tf32(p0[0] * 0.25f));
                qf[i][s][1] = __float_as_uint(f2tf32(p1[0] * 0.25f));
                qf[i][s][2] = __float_as_uint(f2tf32(p0[4] * 0.25f));
                qf[i][s][3] = __float_as_uint(f2tf32(p1[4] * 0.25f));
            }
    }

    float oacc[2][2][4] = {};
    float lsum[4] = {0.f, 0.f, 0.f, 0.f};

    #pragma unroll 1
    for (int tile = 0; tile < 16; tile++) {
        int bi = tile & 1;
        if (tile < 15) cp_wait1(); else cp_wait0();
        __syncthreads();

        #pragma unroll
        for (int j = 0; j < 4; j++) {
            // ---- QK^T for this 8-key slice ------------------------------
            float sacc0[4] = {0.f, 0.f, 0.f, 0.f};
            float sacc1[4] = {0.f, 0.f, 0.f, 0.f};
            #pragma unroll
            for (int s = 0; s < 2; s++) {
                uint32_t bf[2];
                bf[0] = __float_as_uint(S.Ks[bi][8 * j + g][h * 16 + 8 * s + tig]);
                bf[1] = __float_as_uint(S.Ks[bi][8 * j + g][h * 16 + 8 * s + tig + 4]);
                mma_tf32(sacc0, qf[0][s], bf);
                mma_tf32(sacc1, qf[1][s], bf);
            }

            // ---- mask + exp ---------------------------------------------
            int c = 8 * j + 2 * tig;
            float2 w00 = *(const float2*)&S.Wm[bi][g][c];
            float2 w01 = *(const float2*)&S.Wm[bi][g + 8][c];
            float2 w10 = *(const float2*)&S.Wm[bi][g + 16][c];
            float2 w11 = *(const float2*)&S.Wm[bi][g + 24][c];
            float p00 = __expf(fmaf(w00.x, is0, sacc0[0]));
            float p01 = __expf(fmaf(w00.y, is0, sacc0[1]));
            float p02 = __expf(fmaf(w01.x, is1, sacc0[2]));
            float p03 = __expf(fmaf(w01.y, is1, sacc0[3]));
            float p10 = __expf(fmaf(w10.x, is2, sacc1[0]));
            float p11 = __expf(fmaf(w10.y, is2, sacc1[1]));
            float p12 = __expf(fmaf(w11.x, is3, sacc1[2]));
            float p13 = __expf(fmaf(w11.y, is3, sacc1[3]));
            lsum[0] += p00 + p01;
            lsum[1] += p02 + p03;
            lsum[2] += p10 + p11;
            lsum[3] += p12 + p13;

            // ---- C-frag -> A-frag relayout via shuffles -----------------
            uint32_t af0[4], af1[4];
            af0[0] = relay(p00, p01, src0, odd);
            af0[1] = relay(p02, p03, src0, odd);
            af0[2] = relay(p00, p01, src1, odd);
            af0[3] = relay(p02, p03, src1, odd);
            af1[0] = relay(p10, p11, src0, odd);
            af1[1] = relay(p12, p13, src0, odd);
            af1[2] = relay(p10, p11, src1, odd);
            af1[3] = relay(p12, p13, src1, odd);

            // ---- PV for this key slice ----------------------------------
            uint32_t bv0[2], bv1[2];
            bv0[0] = __float_as_uint(S.Vs[bi][8 * j + tig][h * 16 + g]);
            bv0[1] = __float_as_uint(S.Vs[bi][8 * j + tig + 4][h * 16 + g]);
            bv1[0] = __float_as_uint(S.Vs[bi][8 * j + tig][h * 16 + 8 + g]);
            bv1[1] = __float_as_uint(S.Vs[bi][8 * j + tig + 4][h * 16 + 8 + g]);
            mma_tf32(oacc[0][0], af0, bv0);
            mma_tf32(oacc[0][1], af0, bv1);
            mma_tf32(oacc[1][0], af1, bv0);
            mma_tf32(oacc[1][1], af1, bv1);
        }

        __syncthreads();
        if (tile + 2 < 16) {
            mha_issue(S, bi, kvbase, mbase, msta + (tile + 2) * 32, t);
            cp_commit();
        }
    }

    // ---- finalize: quad-reduce l, write UNNORMALIZED partials -----------
    #pragma unroll
    for (int k = 0; k < 4; k++) {
        lsum[k] += __shfl_xor_sync(0xffffffffu, lsum[k], 1);
        lsum[k] += __shfl_xor_sync(0xffffffffu, lsum[k], 2);
    }
    #pragma unroll
    for (int i = 0; i < 2; i++) {
        #pragma unroll
        for (int jd = 0; jd < 2; jd++) {
            size_t base0 = ((size_t)b * N_ + n0 + 16 * i + g) * 128
                           + h * 16 + 8 * jd + 2 * tig;
            size_t base1 = base0 + (size_t)8 * 128;
            *(float2*)&Op[base0] = make_float2(oacc[i][jd][0], oacc[i][jd][1]);
            *(float2*)&Op[base1] = make_float2(oacc[i][jd][2], oacc[i][jd][3]);
        }
    }
    if (tig == 0) {
        Lp[((size_t)(b * N_ + n0 + g)) * 8 + h]      = lsum[0];
        Lp[((size_t)(b * N_ + n0 + 8 + g)) * 8 + h]  = lsum[1];
        Lp[((size_t)(b * N_ + n0 + 16 + g)) * 8 + h] = lsum[2];
        Lp[((size_t)(b * N_ + n0 + 24 + g)) * 8 + h] = lsum[3];
    }
}

// ---------------------------------------------------------------------------
// Combine split-K partials: O = (OA + OB) / (LA + LB)
// ---------------------------------------------------------------------------
__global__ __launch_bounds__(256) void combine_kernel(
    const float* __restrict__ OA, const float* __restrict__ OB,
    const float* __restrict__ LA, const float* __restrict__ LB,
    float* __restrict__ O)
{
    int f = blockIdx.x * 256 + threadIdx.x;   // float4 index
    int e = f << 2;
    int row = e >> 7;                          // b*N + n
    int h   = (e & 127) >> 4;
    float inv = 1.0f / (LA[(size_t)row * 8 + h] + LB[(size_t)row * 8 + h]);
    float4 a = ((const float4*)OA)[f];
    float4 b = ((const float4*)OB)[f];
    float4 o;
    o.x = (a.x + b.x) * inv; o.y = (a.y + b.y) * inv;
    o.z = (a.z + b.z) * inv; o.w = (a.w + b.w) * inv;
    ((float4*)O)[f] = o;
}

// ---------------------------------------------------------------------------
extern "C" void kernel_launch(void* const* d_in, const int* in_sizes, int n_in,
                              void* d_out, int out_size)
{
    const float* H     = (const float*)d_in[0];
    const float* A     = (const float*)d_in[1];
    const float* W_lin = (const float*)d_in[2];
    const float* b_lin = (const float*)d_in[3];
    const float* W_in  = (const float*)d_in[4];
    const float* b_in  = (const float*)d_in[5];
    const float* W_out = (const float*)d_in[6];
    const float* b_out = (const float*)d_in[7];
    const float* W_fin = (const float*)d_in[8];
    const float* b_fin = (const float*)d_in[9];
    float* out = (float*)d_out;

    float *Hp, *Hpr, *qkvp, *attnp, *rowsump, *oAp, *oBp, *lAp, *lBp, *op, *o2p;
    cudaGetSymbolAddress((void**)&Hp,      g_Hp);
    cudaGetSymbolAddress((void**)&Hpr,     g_Hpr);
    cudaGetSymbolAddress((void**)&qkvp,    g_qkv);
    cudaGetSymbolAddress((void**)&attnp,   g_attn);
    cudaGetSymbolAddress((void**)&rowsump, g_rowsum);
    cudaGetSymbolAddress((void**)&oAp,     g_oA);
    cudaGetSymbolAddress((void**)&oBp,     g_oB);
    cudaGetSymbolAddress((void**)&lAp,     g_lA);
    cudaGetSymbolAddress((void**)&lBp,     g_lB);
    cudaGetSymbolAddress((void**)&op,      g_o);
    cudaGetSymbolAddress((void**)&o2p,     g_o2);

    static int smem_set = 0;
    if (!smem_set) {
        cudaFuncSetAttribute(mha_tc, cudaFuncAttributeMaxDynamicSharedMemorySize,
                             (int)sizeof(MhaSmem));
        cudaFuncSetAttribute(gated_tc, cudaFuncAttributeMaxDynamicSharedMemorySize,
                             (int)sizeof(GatedSmem));
        smem_set = 1;
    }

    // 1. Hp = H @ W_lin + b_lin               (8192 x 128)
    gemm_bias<<<dim3(128, 1), 256>>>(H, W_lin, b_lin, Hp, 128);
    // 2. qkv = Hp @ W_in + b_in               (8192 x 384)
    gemm_bias<<<dim3(128, 3), 256>>>(Hp, W_in, b_in, qkvp, 384);
    // 3. pre-round to tf32 (makes cp.async truncation lossless)
    round_tf32<<<B_ * N_ * E_ / (4 * 256), 256>>>(Hp, Hpr);
    round_tf32<<<B_ * N_ * 3 * E_ / (4 * 256), 256>>>(qkvp, qkvp);
    // 4. rowsum = 0
    cudaMemsetAsync(rowsump, 0, B_ * N_ * sizeof(float));
    // 5. gated scores: e = exp(leaky(Hpr Hpr^T) * A), rowsum += partials
    gated_tc<<<dim3(8, 16, 8), 256, sizeof(GatedSmem)>>>(Hpr, A, attnp, rowsump);
    // 6. tensor-core fused MHA split-K -> unnormalized partials
    mha_tc<<<dim3(32, 8, 2), 256, sizeof(MhaSmem)>>>(
        qkvp, attnp, rowsump, oAp, oBp, lAp, lBp);
    // 7. combine partials -> o
    combine_kernel<<<B_ * N_ * E_ / (4 * 256), 256>>>(oAp, oBp, lAp, lBp, op);
    // 8. o2 = o @ W_out + b_out
    gemm_bias<<<dim3(128, 1), 256>>>(op, W_out, b_out, o2p, 128);
    // 9. out = o2 @ W_fin + b_fin
    gemm_bias<<<dim3(128, 1), 256>>>(o2p, W_fin, b_fin, out, 128);
}

// round 12
// speedup vs baseline: 1.2500x; 1.2500x over previous
#include <cuda_runtime.h>
#include <math.h>
#include <stdint.h>

// Problem constants
#define B_ 8
#define N_ 1024
#define E_ 128

// ---------------- helpers ---------------------------------------------------
__device__ __forceinline__ uint32_t saddr(const void* p) {
    return (uint32_t)__cvta_generic_to_shared(p);
}
__device__ __forceinline__ float f2tf32(float x) {
    uint32_t r; asm("cvt.rna.tf32.f32 %0, %1;" : "=r"(r) : "f"(x));
    return __uint_as_float(r);
}
__device__ __forceinline__ void mma_tf32(float* d, const uint32_t* a,
                                         const uint32_t* b) {
    asm volatile(
        "mma.sync.aligned.m16n8k8.row.col.f32.tf32.tf32.f32 "
        "{%0,%1,%2,%3}, {%4,%5,%6,%7}, {%8,%9}, {%0,%1,%2,%3};\n"
        : "+f"(d[0]), "+f"(d[1]), "+f"(d[2]), "+f"(d[3])
        : "r"(a[0]), "r"(a[1]), "r"(a[2]), "r"(a[3]), "r"(b[0]), "r"(b[1]));
}
__device__ __forceinline__ void cpa16(uint32_t dst, const void* src) {
    asm volatile("cp.async.cg.shared.global [%0], [%1], 16;"
                 :: "r"(dst), "l"(src));
}
__device__ __forceinline__ void cp_commit() {
    asm volatile("cp.async.commit_group;");
}
__device__ __forceinline__ void cp_wait1() {
    asm volatile("cp.async.wait_group 1;");
}
__device__ __forceinline__ void cp_wait0() {
    asm volatile("cp.async.wait_group 0;");
}
// C-frag (c0,c1 at cols 2t,2t+1) -> A-frag (col t) relayout + rna cvt
__device__ __forceinline__ uint32_t relay(float c0, float c1, int src, bool odd) {
    float x = __shfl_sync(0xffffffffu, c0, src);
    float y = __shfl_sync(0xffffffffu, c1, src);
    uint32_t r;
    asm("cvt.rna.tf32.f32 %0, %1;" : "=r"(r) : "f"(odd ? y : x));
    return r;
}

// ---------------- scratch (static device globals; no allocation) ----------
__device__ float g_Hr[B_ * N_ * E_];            // rounded H
__device__ float g_Hp[B_ * N_ * E_];            // rounded Hp
__device__ float g_qkv[B_ * N_ * 3 * E_];       // rounded qkv
__device__ float g_attn[(size_t)B_ * N_ * N_];  // unnormalized exp
__device__ float g_rowsum[B_ * N_];
__device__ float g_oA[B_ * N_ * E_];            // split-K partials
__device__ float g_oB[B_ * N_ * E_];
__device__ float g_lA[B_ * N_ * 8];
__device__ float g_lB[B_ * N_ * 8];
__device__ float g_o[B_ * N_ * E_];             // combined MHA out (rounded)
__device__ float g_o2[B_ * N_ * E_];            // out-proj out (rounded)
// transposed + rounded weights: Wt[c][k] = tf32(W[k][c])
__device__ float g_WtLin[E_ * E_];
__device__ float g_WtIn[3 * E_ * E_];
__device__ float g_WtOut[E_ * E_];
__device__ float g_WtFin[E_ * E_];

// ---------------------------------------------------------------------------
// rna tf32 rounding pass (for H)
// ---------------------------------------------------------------------------
__global__ __launch_bounds__(256) void round_tf32(
    const float* __restrict__ src, float* __restrict__ dst)
{
    int i = blockIdx.x * 256 + threadIdx.x;
    float4 v = ((const float4*)src)[i];
    v.x = f2tf32(v.x); v.y = f2tf32(v.y);
    v.z = f2tf32(v.z); v.w = f2tf32(v.w);
    ((float4*)dst)[i] = v;
}

// ---------------------------------------------------------------------------
// Weight prep: Wt[c*128 + k] = tf32(W[k*NC + c]);  K fixed = 128
// ---------------------------------------------------------------------------
__global__ __launch_bounds__(256) void prep_wt(
    const float* __restrict__ W, float* __restrict__ Wt, int NC)
{
    int idx = blockIdx.x * 256 + threadIdx.x;   // over K*NC
    int k = idx / NC, c = idx % NC;
    Wt[c * 128 + k] = f2tf32(W[idx]);
}

// ---------------------------------------------------------------------------
// Tensor-core GEMM + bias:  C[M x NC] = A[M x 128] @ W[128 x NC] + bias
// A pre-rounded tf32; Wt transposed+rounded [NC x 128].
// BM=64, BN=64; 8 warps = 2(m) x 4(n); cp.async double-buffered.
// grid = (M/64, NC/64). round_out: rna-round C values.
// ---------------------------------------------------------------------------
struct GemmSmem {
    float As[2][64][36];
    float Bs[2][64][36];
};

__device__ __forceinline__ void gemm_issue(
    GemmSmem& S, int bi, const float* A, const float* Wt,
    int row0, int col0, int k0, int t)
{
    #pragma unroll
    for (int i = 0; i < 2; i++) {
        int idx = t + i * 256;
        int r = idx >> 3, kk = (idx & 7) << 2;
        cpa16(saddr(&S.As[bi][r][kk]), &A[(size_t)(row0 + r) * 128 + k0 + kk]);
        cpa16(saddr(&S.Bs[bi][r][kk]), &Wt[(size_t)(col0 + r) * 128 + k0 + kk]);
    }
}

__global__ __launch_bounds__(256, 3) void gemm_tc(
    const float* __restrict__ A, const float* __restrict__ Wt,
    const float* __restrict__ bias, float* __restrict__ C,
    int NC, int round_out)
{
    __shared__ GemmSmem S;

    int row0 = blockIdx.x * 64;
    int col0 = blockIdx.y * 64;
    int t    = threadIdx.x;
    int w    = t >> 5;
    int lane = t & 31;
    int g    = lane >> 2;
    int tig  = lane & 3;
    int wm   = (w & 1) * 32;
    int wn   = (w >> 1) * 16;

    gemm_issue(S, 0, A, Wt, row0, col0, 0, t);  cp_commit();
    gemm_issue(S, 1, A, Wt, row0, col0, 32, t); cp_commit();

    float acc[2][2][4] = {};   // [mt][nt][4]

    #pragma unroll 1
    for (int c = 0; c < 4; c++) {
        int bi = c & 1;
        if (c < 3) cp_wait1(); else cp_wait0();
        __syncthreads();

        #pragma unroll
        for (int s = 0; s < 4; s++) {
            uint32_t af[2][4], bf[2][2];
            #pragma unroll
            for (int mt = 0; mt < 2; mt++) {
                const float* base = &S.As[bi][wm + 16 * mt + g][8 * s + tig];
                af[mt][0] = __float_as_uint(base[0]);
                af[mt][1] = __float_as_uint(base[8 * 36]);
                af[mt][2] = __float_as_uint(base[4]);
                af[mt][3] = __float_as_uint(base[8 * 36 + 4]);
            }
            #pragma unroll
            for (int nt = 0; nt < 2; nt++) {
                const float* base = &S.Bs[bi][wn + 8 * nt + g][8 * s + tig];
                bf[nt][0] = __float_as_uint(base[0]);
                bf[nt][1] = __float_as_uint(base[4]);
            }
            #pragma unroll
            for (int mt = 0; mt < 2; mt++)
                #pragma unroll
                for (int nt = 0; nt < 2; nt++)
                    mma_tf32(acc[mt][nt], af[mt], bf[nt]);
        }

        __syncthreads();
        if (c + 2 < 4) {
            gemm_issue(S, bi, A, Wt, row0, col0, (c + 2) * 32, t);
            cp_commit();
        }
    }

    // epilogue: + bias, optional rna rounding
    #pragma unroll
    for (int mt = 0; mt < 2; mt++) {
        #pragma unroll
        for (int eh = 0; eh < 2; eh++) {
            int row = row0 + wm + 16 * mt + 8 * eh + g;
            #pragma unroll
            for (int nt = 0; nt < 2; nt++) {
                int col = col0 + wn + 8 * nt + 2 * tig;
                float2 bv = *(const float2*)&bias[col];
                float v0 = acc[mt][nt][2 * eh]     + bv.x;
                float v1 = acc[mt][nt][2 * eh + 1] + bv.y;
                if (round_out) { v0 = f2tf32(v0); v1 = f2tf32(v1); }
                *(float2*)&C[(size_t)row * NC + col] = make_float2(v0, v1);
            }
        }
    }
}

// ---------------------------------------------------------------------------
// Tensor-core gated scores + fused exp + row-sum, cp.async double-buffered.
// Block tile 128(n) x 64(m); 8 warps = 2(n) x 4(m). grid = (8, 16, 8).
// ---------------------------------------------------------------------------
struct GatedSmem {
    float Ns[2][128][36];
    float Ms[2][64][36];
};

__device__ __forceinline__ void gated_issue(
    GatedSmem& S, int bi, const float* Hb, int n0, int m0, int k0, int t)
{
    #pragma unroll
    for (int i = 0; i < 4; i++) {
        int idx = t + i * 256;
        int r = idx >> 3, kk = (idx & 7) << 2;
        cpa16(saddr(&S.Ns[bi][r][kk]), &Hb[(size_t)(n0 + r) * 128 + k0 + kk]);
    }
    #pragma unroll
    for (int i = 0; i < 2; i++) {
        int idx = t + i * 256;
        int r = idx >> 3, kk = (idx & 7) << 2;
        cpa16(saddr(&S.Ms[bi][r][kk]), &Hb[(size_t)(m0 + r) * 128 + k0 + kk]);
    }
}

__global__ __launch_bounds__(256, 3) void gated_tc(
    const float* __restrict__ Hpr, const float* __restrict__ Adj,
    float* __restrict__ out, float* __restrict__ rowsum)
{
    extern __shared__ char gs_raw[];
    GatedSmem& S = *reinterpret_cast<GatedSmem*>(gs_raw);

    int b  = blockIdx.z;
    int n0 = blockIdx.x * 128;
    int m0 = blockIdx.y * 64;
    const float* Hb = Hpr + (size_t)b * N_ * E_;

    int t    = threadIdx.x;
    int w    = t >> 5;
    int lane = t & 31;
    int g    = lane >> 2;
    int tig  = lane & 3;
    int wn   = (w & 1) * 64;
    int wm   = (w >> 1) * 16;

    gated_issue(S, 0, Hb, n0, m0, 0, t);  cp_commit();
    gated_issue(S, 1, Hb, n0, m0, 32, t); cp_commit();

    float acc[4][2][4] = {};

    #pragma unroll 1
    for (int c = 0; c < 4; c++) {
        int bi = c & 1;
        if (c < 3) cp_wait1(); else cp_wait0();
        __syncthreads();

        #pragma unroll
        for (int s = 0; s < 4; s++) {
            uint32_t af[4][4], bf[2][2];
            #pragma unroll
            for (int mt = 0; mt < 4; mt++) {
                const float* base = &S.Ns[bi][wn + 16 * mt + g][8 * s + tig];
                af[mt][0] = __float_as_uint(base[0]);
                af[mt][1] = __float_as_uint(base[8 * 36]);
                af[mt][2] = __float_as_uint(base[4]);
                af[mt][3] = __float_as_uint(base[8 * 36 + 4]);
            }
            #pragma unroll
            for (int nt = 0; nt < 2; nt++) {
                const float* base = &S.Ms[bi][wm + 8 * nt + g][8 * s + tig];
                bf[nt][0] = __float_as_uint(base[0]);
                bf[nt][1] = __float_as_uint(base[4]);
            }
            #pragma unroll
            for (int mt = 0; mt < 4; mt++)
                #pragma unroll
                for (int nt = 0; nt < 2; nt++)
                    mma_tf32(acc[mt][nt], af[mt], bf[nt]);
        }

        __syncthreads();
        if (c + 2 < 4) {
            gated_issue(S, bi, Hb, n0, m0, (c + 2) * 32, t);
            cp_commit();
        }
    }

    #pragma unroll
    for (int mt = 0; mt < 4; mt++) {
        #pragma unroll
        for (int eh = 0; eh < 2; eh++) {
            int n = n0 + wn + 16 * mt + g + eh * 8;
            float partial = 0.f;
            #pragma unroll
            for (int nt = 0; nt < 2; nt++) {
                int m = m0 + wm + 8 * nt + 2 * tig;
                size_t addr = ((size_t)b * N_ + n) * N_ + m;
                float2 adj = *(const float2*)&Adj[addr];
                float v0 = acc[mt][nt][2 * eh];
                float v1 = acc[mt][nt][2 * eh + 1];
                v0 = (v0 >= 0.f) ? v0 : 0.2f * v0;
                v1 = (v1 >= 0.f) ? v1 : 0.2f * v1;
                float e0 = __expf(v0 * adj.x);
                float e1 = __expf(v1 * adj.y);
                partial += e0 + e1;
                *(float2*)&out[addr] = make_float2(e0, e1);
            }
            partial += __shfl_xor_sync(0xffffffffu, partial, 1);
            partial += __shfl_xor_sync(0xffffffffu, partial, 2);
            if (tig == 0)
                atomicAdd(&rowsum[(size_t)b * N_ + n], partial);
        }
    }
}

// ---------------------------------------------------------------------------
// Tensor-core fused MHA, split-K(2), shuffle P-relayout.
// Block = 32 queries x 8 heads (warp = head); grid = (N/32, B, 2).
// ---------------------------------------------------------------------------
struct MhaSmem {
    float Ks[2][32][132];
    float Vs[2][32][132];
    float Wm[2][32][36];
};

__device__ __forceinline__ void mha_issue(
    MhaSmem& S, int bi, const float* kvbase, const float* mbase,
    int m0, int t)
{
    int srow = t >> 3;
    int sc16 = (t & 7) * 16;
    int mc4  = (t & 7) * 4;
    const float* kr = kvbase + (size_t)(m0 + srow) * 384 + 128 + sc16;
    uint32_t kd = saddr(&S.Ks[bi][srow][sc16]);
    uint32_t vd = saddr(&S.Vs[bi][srow][sc16]);
    #pragma unroll
    for (int c = 0; c < 16; c += 4) {
        cpa16(kd + c * 4, kr + c);
        cpa16(vd + c * 4, kr + 128 + c);
    }
    cpa16(saddr(&S.Wm[bi][srow][mc4]),
          mbase + (size_t)srow * N_ + m0 + mc4);
}

__global__ void __launch_bounds__(256, 3) mha_tc(
    const float* __restrict__ qkv, const float* __restrict__ attn,
    const float* __restrict__ rowsum,
    float* __restrict__ OA, float* __restrict__ OB,
    float* __restrict__ LA, float* __restrict__ LB)
{
    extern __shared__ char smem_raw[];
    MhaSmem& S = *reinterpret_cast<MhaSmem*>(smem_raw);

    int b    = blockIdx.y;
    int n0   = blockIdx.x * 32;
    int msta = blockIdx.z * 512;
    int t    = threadIdx.x;
    int h    = t >> 5;
    int lane = t & 31;
    int g    = lane >> 2;
    int tig  = lane & 3;
    int src0 = (lane & 28) | (tig >> 1);
    int src1 = src0 + 2;
    bool odd = tig & 1;

    float* Op = blockIdx.z ? OB : OA;
    float* Lp = blockIdx.z ? LB : LA;

    const float* kvbase = qkv + (size_t)b * N_ * 384;
    const float* mbase  = attn + ((size_t)b * N_ + n0) * N_;

    mha_issue(S, 0, kvbase, mbase, msta, t);      cp_commit();
    mha_issue(S, 1, kvbase, mbase, msta + 32, t); cp_commit();

    const float* rsb = rowsum + (size_t)b * N_ + n0;
    float is0 = 1.0f / rsb[g];
    float is1 = 1.0f / rsb[g + 8];
    float is2 = 1.0f / rsb[g + 16];
    float is3 = 1.0f / rsb[g + 24];

    uint32_t qf[2][2][4];
    {
        const float* qbase = qkv + ((size_t)b * N_ + n0) * 384 + h * 16;
        #pragma unroll
        for (int i = 0; i < 2; i++)
            #pragma unroll
            for (int s = 0; s < 2; s++) {
                const float* p0 = qbase + (size_t)(16 * i + g) * 384 + 8 * s + tig;
                const float* p1 = p0 + 8 * 384;
                qf[i][s][0] = __float_as_uint(f2tf32(p0[0] * 0.25f));
                qf[i][s][1] = __float_as_uint(f2tf32(p1[0] * 0.25f));
                qf[i][s][2] = __float_as_uint(f2tf32(p0[4] * 0.25f));
                qf[i][s][3] = __float_as_uint(f2tf32(p1[4] * 0.25f));
            }
    }

    float oacc[2][2][4] = {};
    float lsum[4] = {0.f, 0.f, 0.f, 0.f};

    #pragma unroll 1
    for (int tile = 0; tile < 16; tile++) {
        int bi = tile & 1;
        if (tile < 15) cp_wait1(); else cp_wait0();
        __syncthreads();

        #pragma unroll
        for (int j = 0; j < 4; j++) {
            float sacc0[4] = {0.f, 0.f, 0.f, 0.f};
            float sacc1[4] = {0.f, 0.f, 0.f, 0.f};
            #pragma unroll
            for (int s = 0; s < 2; s++) {
                uint32_t bf[2];
                bf[0] = __float_as_uint(S.Ks[bi][8 * j + g][h * 16 + 8 * s + tig]);
                bf[1] = __float_as_uint(S.Ks[bi][8 * j + g][h * 16 + 8 * s + tig + 4]);
                mma_tf32(sacc0, qf[0][s], bf);
                mma_tf32(sacc1, qf[1][s], bf);
            }

            int c = 8 * j + 2 * tig;
            float2 w00 = *(const float2*)&S.Wm[bi][g][c];
            float2 w01 = *(const float2*)&S.Wm[bi][g + 8][c];
            float2 w10 = *(const float2*)&S.Wm[bi][g + 16][c];
            float2 w11 = *(const float2*)&S.Wm[bi][g + 24][c];
            float p00 = __expf(fmaf(w00.x, is0, sacc0[0]));
            float p01 = __expf(fmaf(w00.y, is0, sacc0[1]));
            float p02 = __expf(fmaf(w01.x, is1, sacc0[2]));
            float p03 = __expf(fmaf(w01.y, is1, sacc0[3]));
            float p10 = __expf(fmaf(w10.x, is2, sacc1[0]));
            float p11 = __expf(fmaf(w10.y, is2, sacc1[1]));
            float p12 = __expf(fmaf(w11.x, is3, sacc1[2]));
            float p13 = __expf(fmaf(w11.y, is3, sacc1[3]));
            lsum[0] += p00 + p01;
            lsum[1] += p02 + p03;
            lsum[2] += p10 + p11;
            lsum[3] += p12 + p13;

            uint32_t af0[4], af1[4];
            af0[0] = relay(p00, p01, src0, odd);
            af0[1] = relay(p02, p03, src0, odd);
            af0[2] = relay(p00, p01, src1, odd);
            af0[3] = relay(p02, p03, src1, odd);
            af1[0] = relay(p10, p11, src0, odd);
            af1[1] = relay(p12, p13, src0, odd);
            af1[2] = relay(p10, p11, src1, odd);
            af1[3] = relay(p12, p13, src1, odd);

            uint32_t bv0[2], bv1[2];
            bv0[0] = __float_as_uint(S.Vs[bi][8 * j + tig][h * 16 + g]);
            bv0[1] = __float_as_uint(S.Vs[bi][8 * j + tig + 4][h * 16 + g]);
            bv1[0] = __float_as_uint(S.Vs[bi][8 * j + tig][h * 16 + 8 + g]);
            bv1[1] = __float_as_uint(S.Vs[bi][8 * j + tig + 4][h * 16 + 8 + g]);
            mma_tf32(oacc[0][0], af0, bv0);
            mma_tf32(oacc[0][1], af0, bv1);
            mma_tf32(oacc[1][0], af1, bv0);
            mma_tf32(oacc[1][1], af1, bv1);
        }

        __syncthreads();
        if (tile + 2 < 16) {
            mha_issue(S, bi, kvbase, mbase, msta + (tile + 2) * 32, t);
            cp_commit();
        }
    }

    #pragma unroll
    for (int k = 0; k < 4; k++) {
        lsum[k] += __shfl_xor_sync(0xffffffffu, lsum[k], 1);
        lsum[k] += __shfl_xor_sync(0xffffffffu, lsum[k], 2);
    }
    #pragma unroll
    for (int i = 0; i < 2; i++) {
        #pragma unroll
        for (int jd = 0; jd < 2; jd++) {
            size_t base0 = ((size_t)b * N_ + n0 + 16 * i + g) * 128
                           + h * 16 + 8 * jd + 2 * tig;
            size_t base1 = base0 + (size_t)8 * 128;
            *(float2*)&Op[base0] = make_float2(oacc[i][jd][0], oacc[i][jd][1]);
            *(float2*)&Op[base1] = make_float2(oacc[i][jd][2], oacc[i][jd][3]);
        }
    }
    if (tig == 0) {
        Lp[((size_t)(b * N_ + n0 + g)) * 8 + h]      = lsum[0];
        Lp[((size_t)(b * N_ + n0 + 8 + g)) * 8 + h]  = lsum[1];
        Lp[((size_t)(b * N_ + n0 + 16 + g)) * 8 + h] = lsum[2];
        Lp[((size_t)(b * N_ + n0 + 24 + g)) * 8 + h] = lsum[3];
    }
}

// ---------------------------------------------------------------------------
// Combine split-K partials: O = round_tf32((OA + OB) / (LA + LB))
// ---------------------------------------------------------------------------
__global__ __launch_bounds__(256) void combine_kernel(
    const float* __restrict__ OA, const float* __restrict__ OB,
    const float* __restrict__ LA, const float* __restrict__ LB,
    float* __restrict__ O)
{
    int f = blockIdx.x * 256 + threadIdx.x;
    int e = f << 2;
    int row = e >> 7;
    int h   = (e & 127) >> 4;
    float inv = 1.0f / (LA[(size_t)row * 8 + h] + LB[(size_t)row * 8 + h]);
    float4 a = ((const float4*)OA)[f];
    float4 b = ((const float4*)OB)[f];
    float4 o;
    o.x = f2tf32((a.x + b.x) * inv); o.y = f2tf32((a.y + b.y) * inv);
    o.z = f2tf32((a.z + b.z) * inv); o.w = f2tf32((a.w + b.w) * inv);
    ((float4*)O)[f] = o;
}

// ---------------------------------------------------------------------------
extern "C" void kernel_launch(void* const* d_in, const int* in_sizes, int n_in,
                              void* d_out, int out_size)
{
    const float* H     = (const float*)d_in[0];
    const float* A     = (const float*)d_in[1];
    const float* W_lin = (const float*)d_in[2];
    const float* b_lin = (const float*)d_in[3];
    const float* W_in  = (const float*)d_in[4];
    const float* b_in  = (const float*)d_in[5];
    const float* W_out = (const float*)d_in[6];
    const float* b_out = (const float*)d_in[7];
    const float* W_fin = (const float*)d_in[8];
    const float* b_fin = (const float*)d_in[9];
    float* out = (float*)d_out;

    float *Hr, *Hp, *qkvp, *attnp, *rowsump, *oAp, *oBp, *lAp, *lBp, *op, *o2p;
    float *wtLin, *wtIn, *wtOut, *wtFin;
    cudaGetSymbolAddress((void**)&Hr,      g_Hr);
    cudaGetSymbolAddress((void**)&Hp,      g_Hp);
    cudaGetSymbolAddress((void**)&qkvp,    g_qkv);
    cudaGetSymbolAddress((void**)&attnp,   g_attn);
    cudaGetSymbolAddress((void**)&rowsump, g_rowsum);
    cudaGetSymbolAddress((void**)&oAp,     g_oA);
    cudaGetSymbolAddress((void**)&oBp,     g_oB);
    cudaGetSymbolAddress((void**)&lAp,     g_lA);
    cudaGetSymbolAddress((void**)&lBp,     g_lB);
    cudaGetSymbolAddress((void**)&op,      g_o);
    cudaGetSymbolAddress((void**)&o2p,     g_o2);
    cudaGetSymbolAddress((void**)&wtLin,   g_WtLin);
    cudaGetSymbolAddress((void**)&wtIn,    g_WtIn);
    cudaGetSymbolAddress((void**)&wtOut,   g_WtOut);
    cudaGetSymbolAddress((void**)&wtFin,   g_WtFin);

    static int smem_set = 0;
    if (!smem_set) {
        cudaFuncSetAttribute(mha_tc, cudaFuncAttributeMaxDynamicSharedMemorySize,
                             (int)sizeof(MhaSmem));
        cudaFuncSetAttribute(gated_tc, cudaFuncAttributeMaxDynamicSharedMemorySize,
                             (int)sizeof(GatedSmem));
        smem_set = 1;
    }

    // 0. prep: round H; transpose+round weights
    round_tf32<<<B_ * N_ * E_ / (4 * 256), 256>>>(H, Hr);
    prep_wt<<<128 * 128 / 256, 256>>>(W_lin, wtLin, 128);
    prep_wt<<<128 * 384 / 256, 256>>>(W_in,  wtIn,  384);
    prep_wt<<<128 * 128 / 256, 256>>>(W_out, wtOut, 128);
    prep_wt<<<128 * 128 / 256, 256>>>(W_fin, wtFin, 128);
    cudaMemsetAsync(rowsump, 0, B_ * N_ * sizeof(float));

    // 1. Hp = round(Hr @ W_lin + b_lin)
    gemm_tc<<<dim3(128, 2), 256>>>(Hr, wtLin, b_lin, Hp, 128, 1);
    // 2. qkv = round(Hp @ W_in + b_in)
    gemm_tc<<<dim3(128, 6), 256>>>(Hp, wtIn, b_in, qkvp, 384, 1);
    // 3. gated scores: e = exp(leaky(Hp Hp^T) * A), rowsum += partials
    gated_tc<<<dim3(8, 16, 8), 256, sizeof(GatedSmem)>>>(Hp, A, attnp, rowsump);
    // 4. tensor-core fused MHA split-K -> unnormalized partials
    mha_tc<<<dim3(32, 8, 2), 256, sizeof(MhaSmem)>>>(
        qkvp, attnp, rowsump, oAp, oBp, lAp, lBp);
    // 5. combine partials -> o (rounded)
    combine_kernel<<<B_ * N_ * E_ / (4 * 256), 256>>>(oAp, oBp, lAp, lBp, op);
    // 6. o2 = round(o @ W_out + b_out)
    gemm_tc<<<dim3(128, 2), 256>>>(op, wtOut, b_out, o2p, 128, 1);
    // 7. out = o2 @ W_fin + b_fin   (final: no rounding)
    gemm_tc<<<dim3(128, 2), 256>>>(o2p, wtFin, b_fin, out, 128, 0);
}

// round 14
// speedup vs baseline: 1.3143x; 1.0514x over previous
#include <cuda_runtime.h>
#include <math.h>
#include <stdint.h>

// Problem constants
#define B_ 8
#define N_ 1024
#define E_ 128

// ---------------- helpers ---------------------------------------------------
__device__ __forceinline__ uint32_t saddr(const void* p) {
    return (uint32_t)__cvta_generic_to_shared(p);
}
__device__ __forceinline__ float f2tf32(float x) {
    uint32_t r; asm("cvt.rna.tf32.f32 %0, %1;" : "=r"(r) : "f"(x));
    return __uint_as_float(r);
}
__device__ __forceinline__ void mma_tf32(float* d, const uint32_t* a,
                                         const uint32_t* b) {
    asm volatile(
        "mma.sync.aligned.m16n8k8.row.col.f32.tf32.tf32.f32 "
        "{%0,%1,%2,%3}, {%4,%5,%6,%7}, {%8,%9}, {%0,%1,%2,%3};\n"
        : "+f"(d[0]), "+f"(d[1]), "+f"(d[2]), "+f"(d[3])
        : "r"(a[0]), "r"(a[1]), "r"(a[2]), "r"(a[3]), "r"(b[0]), "r"(b[1]));
}
__device__ __forceinline__ void cpa16(uint32_t dst, const void* src) {
    asm volatile("cp.async.cg.shared.global [%0], [%1], 16;"
                 :: "r"(dst), "l"(src));
}
__device__ __forceinline__ void cp_commit() {
    asm volatile("cp.async.commit_group;");
}
__device__ __forceinline__ void cp_wait1() {
    asm volatile("cp.async.wait_group 1;");
}
__device__ __forceinline__ void cp_wait0() {
    asm volatile("cp.async.wait_group 0;");
}
// C-frag (c0,c1 at cols 2t,2t+1) -> A-frag (col t) relayout + rna cvt
__device__ __forceinline__ uint32_t relay(float c0, float c1, int src, bool odd) {
    float x = __shfl_sync(0xffffffffu, c0, src);
    float y = __shfl_sync(0xffffffffu, c1, src);
    uint32_t r;
    asm("cvt.rna.tf32.f32 %0, %1;" : "=r"(r) : "f"(odd ? y : x));
    return r;
}

// ---------------- scratch (static device globals; no allocation) ----------
__device__ float g_Hr[B_ * N_ * E_];            // rounded H
__device__ float g_Hp[B_ * N_ * E_];            // rounded Hp
__device__ float g_qkv[B_ * N_ * 3 * E_];       // rounded qkv
__device__ float g_attn[(size_t)B_ * N_ * N_];  // unnormalized exp
__device__ float g_rowsum[B_ * N_];
__device__ float g_oA[B_ * N_ * E_];            // split-K partials
__device__ float g_oB[B_ * N_ * E_];
__device__ float g_lA[B_ * N_ * 8];
__device__ float g_lB[B_ * N_ * 8];
__device__ float g_o[B_ * N_ * E_];             // combined MHA out (rounded)
__device__ float g_o2[B_ * N_ * E_];            // out-proj out (rounded)
// transposed + rounded weights: Wt[c][k] = tf32(W[k][c])
__device__ float g_WtLin[E_ * E_];
__device__ float g_WtIn[3 * E_ * E_];
__device__ float g_WtOut[E_ * E_];
__device__ float g_WtFin[E_ * E_];

// ---------------------------------------------------------------------------
// Single consolidated prep launch:
//   blocks [0,1024):      Hr = round(H)            (float4)
//   blocks [1024,1088):   WtLin transpose+round    (128x128)
//   blocks [1088,1280):   WtIn  transpose+round    (128x384)
//   blocks [1280,1344):   WtOut transpose+round
//   blocks [1344,1408):   WtFin transpose+round
//   blocks [1408,1416):   rowsum = 0               (float4)
// ---------------------------------------------------------------------------
__global__ __launch_bounds__(256) void prep_all(
    const float* __restrict__ H,
    const float* __restrict__ W_lin, const float* __restrict__ W_in,
    const float* __restrict__ W_out, const float* __restrict__ W_fin,
    float* __restrict__ Hr,
    float* __restrict__ wtLin, float* __restrict__ wtIn,
    float* __restrict__ wtOut, float* __restrict__ wtFin,
    float* __restrict__ rowsum)
{
    int bid = blockIdx.x;
    int t   = threadIdx.x;
    if (bid < 1024) {
        int i = bid * 256 + t;
        float4 v = ((const float4*)H)[i];
        v.x = f2tf32(v.x); v.y = f2tf32(v.y);
        v.z = f2tf32(v.z); v.w = f2tf32(v.w);
        ((float4*)Hr)[i] = v;
    } else if (bid < 1088) {
        int idx = (bid - 1024) * 256 + t;       // over 128*128
        int k = idx >> 7, c = idx & 127;
        wtLin[c * 128 + k] = f2tf32(W_lin[idx]);
    } else if (bid < 1280) {
        int idx = (bid - 1088) * 256 + t;       // over 128*384
        int k = idx / 384, c = idx % 384;
        wtIn[c * 128 + k] = f2tf32(W_in[idx]);
    } else if (bid < 1344) {
        int idx = (bid - 1280) * 256 + t;
        int k = idx >> 7, c = idx & 127;
        wtOut[c * 128 + k] = f2tf32(W_out[idx]);
    } else if (bid < 1408) {
        int idx = (bid - 1344) * 256 + t;
        int k = idx >> 7, c = idx & 127;
        wtFin[c * 128 + k] = f2tf32(W_fin[idx]);
    } else {
        int i = (bid - 1408) * 256 + t;         // 2048 float4 = 8192 floats
        ((float4*)rowsum)[i] = make_float4(0.f, 0.f, 0.f, 0.f);
    }
}

// ---------------------------------------------------------------------------
// Tensor-core GEMM + bias:  C[M x NC] = A[M x 128] @ W[128 x NC] + bias
// A pre-rounded tf32; Wt transposed+rounded [NC x 128].
// BM=64, BN=64; 8 warps = 2(m) x 4(n); cp.async double-buffered.
// grid = (M/64, NC/64). round_out: rna-round C values.
// ---------------------------------------------------------------------------
struct GemmSmem {
    float As[2][64][36];
    float Bs[2][64][36];
};

__device__ __forceinline__ void gemm_issue(
    GemmSmem& S, int bi, const float* A, const float* Wt,
    int row0, int col0, int k0, int t)
{
    #pragma unroll
    for (int i = 0; i < 2; i++) {
        int idx = t + i * 256;
        int r = idx >> 3, kk = (idx & 7) << 2;
        cpa16(saddr(&S.As[bi][r][kk]), &A[(size_t)(row0 + r) * 128 + k0 + kk]);
        cpa16(saddr(&S.Bs[bi][r][kk]), &Wt[(size_t)(col0 + r) * 128 + k0 + kk]);
    }
}

__global__ __launch_bounds__(256, 3) void gemm_tc(
    const float* __restrict__ A, const float* __restrict__ Wt,
    const float* __restrict__ bias, float* __restrict__ C,
    int NC, int round_out)
{
    __shared__ GemmSmem S;

    int row0 = blockIdx.x * 64;
    int col0 = blockIdx.y * 64;
    int t    = threadIdx.x;
    int w    = t >> 5;
    int lane = t & 31;
    int g    = lane >> 2;
    int tig  = lane & 3;
    int wm   = (w & 1) * 32;
    int wn   = (w >> 1) * 16;

    gemm_issue(S, 0, A, Wt, row0, col0, 0, t);  cp_commit();
    gemm_issue(S, 1, A, Wt, row0, col0, 32, t); cp_commit();

    float acc[2][2][4] = {};   // [mt][nt][4]

    #pragma unroll 1
    for (int c = 0; c < 4; c++) {
        int bi = c & 1;
        if (c < 3) cp_wait1(); else cp_wait0();
        __syncthreads();

        #pragma unroll
        for (int s = 0; s < 4; s++) {
            uint32_t af[2][4], bf[2][2];
            #pragma unroll
            for (int mt = 0; mt < 2; mt++) {
                const float* base = &S.As[bi][wm + 16 * mt + g][8 * s + tig];
                af[mt][0] = __float_as_uint(base[0]);
                af[mt][1] = __float_as_uint(base[8 * 36]);
                af[mt][2] = __float_as_uint(base[4]);
                af[mt][3] = __float_as_uint(base[8 * 36 + 4]);
            }
            #pragma unroll
            for (int nt = 0; nt < 2; nt++) {
                const float* base = &S.Bs[bi][wn + 8 * nt + g][8 * s + tig];
                bf[nt][0] = __float_as_uint(base[0]);
                bf[nt][1] = __float_as_uint(base[4]);
            }
            #pragma unroll
            for (int mt = 0; mt < 2; mt++)
                #pragma unroll
                for (int nt = 0; nt < 2; nt++)
                    mma_tf32(acc[mt][nt], af[mt], bf[nt]);
        }

        __syncthreads();
        if (c + 2 < 4) {
            gemm_issue(S, bi, A, Wt, row0, col0, (c + 2) * 32, t);
            cp_commit();
        }
    }

    // epilogue: + bias, optional rna rounding
    #pragma unroll
    for (int mt = 0; mt < 2; mt++) {
        #pragma unroll
        for (int eh = 0; eh < 2; eh++) {
            int row = row0 + wm + 16 * mt + 8 * eh + g;
            #pragma unroll
            for (int nt = 0; nt < 2; nt++) {
                int col = col0 + wn + 8 * nt + 2 * tig;
                float2 bv = *(const float2*)&bias[col];
                float v0 = acc[mt][nt][2 * eh]     + bv.x;
                float v1 = acc[mt][nt][2 * eh + 1] + bv.y;
                if (round_out) { v0 = f2tf32(v0); v1 = f2tf32(v1); }
                *(float2*)&C[(size_t)row * NC + col] = make_float2(v0, v1);
            }
        }
    }
}

// ---------------------------------------------------------------------------
// Tensor-core gated scores + fused exp + row-sum, cp.async double-buffered.
// Block tile 128(n) x 64(m); 8 warps = 2(n) x 4(m). grid = (8, 16, 8).
// ---------------------------------------------------------------------------
struct GatedSmem {
    float Ns[2][128][36];
    float Ms[2][64][36];
};

__device__ __forceinline__ void gated_issue(
    GatedSmem& S, int bi, const float* Hb, int n0, int m0, int k0, int t)
{
    #pragma unroll
    for (int i = 0; i < 4; i++) {
        int idx = t + i * 256;
        int r = idx >> 3, kk = (idx & 7) << 2;
        cpa16(saddr(&S.Ns[bi][r][kk]), &Hb[(size_t)(n0 + r) * 128 + k0 + kk]);
    }
    #pragma unroll
    for (int i = 0; i < 2; i++) {
        int idx = t + i * 256;
        int r = idx >> 3, kk = (idx & 7) << 2;
        cpa16(saddr(&S.Ms[bi][r][kk]), &Hb[(size_t)(m0 + r) * 128 + k0 + kk]);
    }
}

__global__ __launch_bounds__(256, 3) void gated_tc(
    const float* __restrict__ Hpr, const float* __restrict__ Adj,
    float* __restrict__ out, float* __restrict__ rowsum)
{
    extern __shared__ char gs_raw[];
    GatedSmem& S = *reinterpret_cast<GatedSmem*>(gs_raw);

    int b  = blockIdx.z;
    int n0 = blockIdx.x * 128;
    int m0 = blockIdx.y * 64;
    const float* Hb = Hpr + (size_t)b * N_ * E_;

    int t    = threadIdx.x;
    int w    = t >> 5;
    int lane = t & 31;
    int g    = lane >> 2;
    int tig  = lane & 3;
    int wn   = (w & 1) * 64;
    int wm   = (w >> 1) * 16;

    gated_issue(S, 0, Hb, n0, m0, 0, t);  cp_commit();
    gated_issue(S, 1, Hb, n0, m0, 32, t); cp_commit();

    float acc[4][2][4] = {};

    #pragma unroll 1
    for (int c = 0; c < 4; c++) {
        int bi = c & 1;
        if (c < 3) cp_wait1(); else cp_wait0();
        __syncthreads();

        #pragma unroll
        for (int s = 0; s < 4; s++) {
            uint32_t af[4][4], bf[2][2];
            #pragma unroll
            for (int mt = 0; mt < 4; mt++) {
                const float* base = &S.Ns[bi][wn + 16 * mt + g][8 * s + tig];
                af[mt][0] = __float_as_uint(base[0]);
                af[mt][1] = __float_as_uint(base[8 * 36]);
                af[mt][2] = __float_as_uint(base[4]);
                af[mt][3] = __float_as_uint(base[8 * 36 + 4]);
            }
            #pragma unroll
            for (int nt = 0; nt < 2; nt++) {
                const float* base = &S.Ms[bi][wm + 8 * nt + g][8 * s + tig];
                bf[nt][0] = __float_as_uint(base[0]);
                bf[nt][1] = __float_as_uint(base[4]);
            }
            #pragma unroll
            for (int mt = 0; mt < 4; mt++)
                #pragma unroll
                for (int nt = 0; nt < 2; nt++)
                    mma_tf32(acc[mt][nt], af[mt], bf[nt]);
        }

        __syncthreads();
        if (c + 2 < 4) {
            gated_issue(S, bi, Hb, n0, m0, (c + 2) * 32, t);
            cp_commit();
        }
    }

    #pragma unroll
    for (int mt = 0; mt < 4; mt++) {
        #pragma unroll
        for (int eh = 0; eh < 2; eh++) {
            int n = n0 + wn + 16 * mt + g + eh * 8;
            float partial = 0.f;
            #pragma unroll
            for (int nt = 0; nt < 2; nt++) {
                int m = m0 + wm + 8 * nt + 2 * tig;
                size_t addr = ((size_t)b * N_ + n) * N_ + m;
                float2 adj = *(const float2*)&Adj[addr];
                float v0 = acc[mt][nt][2 * eh];
                float v1 = acc[mt][nt][2 * eh + 1];
                v0 = (v0 >= 0.f) ? v0 : 0.2f * v0;
                v1 = (v1 >= 0.f) ? v1 : 0.2f * v1;
                float e0 = __expf(v0 * adj.x);
                float e1 = __expf(v1 * adj.y);
                partial += e0 + e1;
                *(float2*)&out[addr] = make_float2(e0, e1);
            }
            partial += __shfl_xor_sync(0xffffffffu, partial, 1);
            partial += __shfl_xor_sync(0xffffffffu, partial, 2);
            if (tig == 0)
                atomicAdd(&rowsum[(size_t)b * N_ + n], partial);
        }
    }
}

// ---------------------------------------------------------------------------
// Tensor-core fused MHA, split-K(2), shuffle P-relayout.
// Block = 32 queries x 8 heads (warp = head); grid = (N/32, B, 2).
// ---------------------------------------------------------------------------
struct MhaSmem {
    float Ks[2][32][132];
    float Vs[2][32][132];
    float Wm[2][32][36];
};

__device__ __forceinline__ void mha_issue(
    MhaSmem& S, int bi, const float* kvbase, const float* mbase,
    int m0, int t)
{
    int srow = t >> 3;
    int sc16 = (t & 7) * 16;
    int mc4  = (t & 7) * 4;
    const float* kr = kvbase + (size_t)(m0 + srow) * 384 + 128 + sc16;
    uint32_t kd = saddr(&S.Ks[bi][srow][sc16]);
    uint32_t vd = saddr(&S.Vs[bi][srow][sc16]);
    #pragma unroll
    for (int c = 0; c < 16; c += 4) {
        cpa16(kd + c * 4, kr + c);
        cpa16(vd + c * 4, kr + 128 + c);
    }
    cpa16(saddr(&S.Wm[bi][srow][mc4]),
          mbase + (size_t)srow * N_ + m0 + mc4);
}

__global__ void __launch_bounds__(256, 3) mha_tc(
    const float* __restrict__ qkv, const float* __restrict__ attn,
    const float* __restrict__ rowsum,
    float* __restrict__ OA, float* __restrict__ OB,
    float* __restrict__ LA, float* __restrict__ LB)
{
    extern __shared__ char smem_raw[];
    MhaSmem& S = *reinterpret_cast<MhaSmem*>(smem_raw);

    int b    = blockIdx.y;
    int n0   = blockIdx.x * 32;
    int msta = blockIdx.z * 512;
    int t    = threadIdx.x;
    int h    = t >> 5;
    int lane = t & 31;
    int g    = lane >> 2;
    int tig  = lane & 3;
    int src0 = (lane & 28) | (tig >> 1);
    int src1 = src0 + 2;
    bool odd = tig & 1;

    float* Op = blockIdx.z ? OB : OA;
    float* Lp = blockIdx.z ? LB : LA;

    const float* kvbase = qkv + (size_t)b * N_ * 384;
    const float* mbase  = attn + ((size_t)b * N_ + n0) * N_;

    mha_issue(S, 0, kvbase, mbase, msta, t);      cp_commit();
    mha_issue(S, 1, kvbase, mbase, msta + 32, t); cp_commit();

    const float* rsb = rowsum + (size_t)b * N_ + n0;
    float is0 = 1.0f / rsb[g];
    float is1 = 1.0f / rsb[g + 8];
    float is2 = 1.0f / rsb[g + 16];
    float is3 = 1.0f / rsb[g + 24];

    uint32_t qf[2][2][4];
    {
        const float* qbase = qkv + ((size_t)b * N_ + n0) * 384 + h * 16;
        #pragma unroll
        for (int i = 0; i < 2; i++)
            #pragma unroll
            for (int s = 0; s < 2; s++) {
                const float* p0 = qbase + (size_t)(16 * i + g) * 384 + 8 * s + tig;
                const float* p1 = p0 + 8 * 384;
                qf[i][s][0] = __float_as_uint(f2tf32(p0[0] * 0.25f));
                qf[i][s][1] = __float_as_uint(f2tf32(p1[0] * 0.25f));
                qf[i][s][2] = __float_as_uint(f2tf32(p0[4] * 0.25f));
                qf[i][s][3] = __float_as_uint(f2tf32(p1[4] * 0.25f));
            }
    }

    float oacc[2][2][4] = {};
    float lsum[4] = {0.f, 0.f, 0.f, 0.f};

    #pragma unroll 1
    for (int tile = 0; tile < 16; tile++) {
        int bi = tile & 1;
        if (tile < 15) cp_wait1(); else cp_wait0();
        __syncthreads();

        #pragma unroll
        for (int j = 0; j < 4; j++) {
            float sacc0[4] = {0.f, 0.f, 0.f, 0.f};
            float sacc1[4] = {0.f, 0.f, 0.f, 0.f};
            #pragma unroll
            for (int s = 0; s < 2; s++) {
                uint32_t bf[2];
                bf[0] = __float_as_uint(S.Ks[bi][8 * j + g][h * 16 + 8 * s + tig]);
                bf[1] = __float_as_uint(S.Ks[bi][8 * j + g][h * 16 + 8 * s + tig + 4]);
                mma_tf32(sacc0, qf[0][s], bf);
                mma_tf32(sacc1, qf[1][s], bf);
            }

            int c = 8 * j + 2 * tig;
            float2 w00 = *(const float2*)&S.Wm[bi][g][c];
            float2 w01 = *(const float2*)&S.Wm[bi][g + 8][c];
            float2 w10 = *(const float2*)&S.Wm[bi][g + 16][c];
            float2 w11 = *(const float2*)&S.Wm[bi][g + 24][c];
            float p00 = __expf(fmaf(w00.x, is0, sacc0[0]));
            float p01 = __expf(fmaf(w00.y, is0, sacc0[1]));
            float p02 = __expf(fmaf(w01.x, is1, sacc0[2]));
            float p03 = __expf(fmaf(w01.y, is1, sacc0[3]));
            float p10 = __expf(fmaf(w10.x, is2, sacc1[0]));
            float p11 = __expf(fmaf(w10.y, is2, sacc1[1]));
            float p12 = __expf(fmaf(w11.x, is3, sacc1[2]));
            float p13 = __expf(fmaf(w11.y, is3, sacc1[3]));
            lsum[0] += p00 + p01;
            lsum[1] += p02 + p03;
            lsum[2] += p10 + p11;
            lsum[3] += p12 + p13;

            uint32_t af0[4], af1[4];
            af0[0] = relay(p00, p01, src0, odd);
            af0[1] = relay(p02, p03, src0, odd);
            af0[2] = relay(p00, p01, src1, odd);
            af0[3] = relay(p02, p03, src1, odd);
            af1[0] = relay(p10, p11, src0, odd);
            af1[1] = relay(p12, p13, src0, odd);
            af1[2] = relay(p10, p11, src1, odd);
            af1[3] = relay(p12, p13, src1, odd);

            uint32_t bv0[2], bv1[2];
            bv0[0] = __float_as_uint(S.Vs[bi][8 * j + tig][h * 16 + g]);
            bv0[1] = __float_as_uint(S.Vs[bi][8 * j + tig + 4][h * 16 + g]);
            bv1[0] = __float_as_uint(S.Vs[bi][8 * j + tig][h * 16 + 8 + g]);
            bv1[1] = __float_as_uint(S.Vs[bi][8 * j + tig + 4][h * 16 + 8 + g]);
            mma_tf32(oacc[0][0], af0, bv0);
            mma_tf32(oacc[0][1], af0, bv1);
            mma_tf32(oacc[1][0], af1, bv0);
            mma_tf32(oacc[1][1], af1, bv1);
        }

        __syncthreads();
        if (tile + 2 < 16) {
            mha_issue(S, bi, kvbase, mbase, msta + (tile + 2) * 32, t);
            cp_commit();
        }
    }

    #pragma unroll
    for (int k = 0; k < 4; k++) {
        lsum[k] += __shfl_xor_sync(0xffffffffu, lsum[k], 1);
        lsum[k] += __shfl_xor_sync(0xffffffffu, lsum[k], 2);
    }
    #pragma unroll
    for (int i = 0; i < 2; i++) {
        #pragma unroll
        for (int jd = 0; jd < 2; jd++) {
            size_t base0 = ((size_t)b * N_ + n0 + 16 * i + g) * 128
                           + h * 16 + 8 * jd + 2 * tig;
            size_t base1 = base0 + (size_t)8 * 128;
            *(float2*)&Op[base0] = make_float2(oacc[i][jd][0], oacc[i][jd][1]);
            *(float2*)&Op[base1] = make_float2(oacc[i][jd][2], oacc[i][jd][3]);
        }
    }
    if (tig == 0) {
        Lp[((size_t)(b * N_ + n0 + g)) * 8 + h]      = lsum[0];
        Lp[((size_t)(b * N_ + n0 + 8 + g)) * 8 + h]  = lsum[1];
        Lp[((size_t)(b * N_ + n0 + 16 + g)) * 8 + h] = lsum[2];
        Lp[((size_t)(b * N_ + n0 + 24 + g)) * 8 + h] = lsum[3];
    }
}

// ---------------------------------------------------------------------------
// Combine split-K partials: O = round_tf32((OA + OB) / (LA + LB))
// ---------------------------------------------------------------------------
__global__ __launch_bounds__(256) void combine_kernel(
    const float* __restrict__ OA, const float* __restrict__ OB,
    const float* __restrict__ LA, const float* __restrict__ LB,
    float* __restrict__ O)
{
    int f = blockIdx.x * 256 + threadIdx.x;
    int e = f << 2;
    int row = e >> 7;
    int h   = (e & 127) >> 4;
    float inv = 1.0f / (LA[(size_t)row * 8 + h] + LB[(size_t)row * 8 + h]);
    float4 a = ((const float4*)OA)[f];
    float4 b = ((const float4*)OB)[f];
    float4 o;
    o.x = f2tf32((a.x + b.x) * inv); o.y = f2tf32((a.y + b.y) * inv);
    o.z = f2tf32((a.z + b.z) * inv); o.w = f2tf32((a.w + b.w) * inv);
    ((float4*)O)[f] = o;
}

// ---------------------------------------------------------------------------
extern "C" void kernel_launch(void* const* d_in, const int* in_sizes, int n_in,
                              void* d_out, int out_size)
{
    const float* H     = (const float*)d_in[0];
    const float* A     = (const float*)d_in[1];
    const float* W_lin = (const float*)d_in[2];
    const float* b_lin = (const float*)d_in[3];
    const float* W_in  = (const float*)d_in[4];
    const float* b_in  = (const float*)d_in[5];
    const float* W_out = (const float*)d_in[6];
    const float* b_out = (const float*)d_in[7];
    const float* W_fin = (const float*)d_in[8];
    const float* b_fin = (const float*)d_in[9];
    float* out = (float*)d_out;

    float *Hr, *Hp, *qkvp, *attnp, *rowsump, *oAp, *oBp, *lAp, *lBp, *op, *o2p;
    float *wtLin, *wtIn, *wtOut, *wtFin;
    cudaGetSymbolAddress((void**)&Hr,      g_Hr);
    cudaGetSymbolAddress((void**)&Hp,      g_Hp);
    cudaGetSymbolAddress((void**)&qkvp,    g_qkv);
    cudaGetSymbolAddress((void**)&attnp,   g_attn);
    cudaGetSymbolAddress((void**)&rowsump, g_rowsum);
    cudaGetSymbolAddress((void**)&oAp,     g_oA);
    cudaGetSymbolAddress((void**)&oBp,     g_oB);
    cudaGetSymbolAddress((void**)&lAp,     g_lA);
    cudaGetSymbolAddress((void**)&lBp,     g_lB);
    cudaGetSymbolAddress((void**)&op,      g_o);
    cudaGetSymbolAddress((void**)&o2p,     g_o2);
    cudaGetSymbolAddress((void**)&wtLin,   g_WtLin);
    cudaGetSymbolAddress((void**)&wtIn,    g_WtIn);
    cudaGetSymbolAddress((void**)&wtOut,   g_WtOut);
    cudaGetSymbolAddress((void**)&wtFin,   g_WtFin);

    static int smem_set = 0;
    if (!smem_set) {
        cudaFuncSetAttribute(mha_tc, cudaFuncAttributeMaxDynamicSharedMemorySize,
                             (int)sizeof(MhaSmem));
        cudaFuncSetAttribute(gated_tc, cudaFuncAttributeMaxDynamicSharedMemorySize,
                             (int)sizeof(GatedSmem));
        smem_set = 1;
    }

    // 0. ONE prep launch: round H, transpose+round all weights, zero rowsum
    prep_all<<<1416, 256>>>(H, W_lin, W_in, W_out, W_fin,
                            Hr, wtLin, wtIn, wtOut, wtFin, rowsump);

    // 1. Hp = round(Hr @ W_lin + b_lin)
    gemm_tc<<<dim3(128, 2), 256>>>(Hr, wtLin, b_lin, Hp, 128, 1);
    // 2. qkv = round(Hp @ W_in + b_in)
    gemm_tc<<<dim3(128, 6), 256>>>(Hp, wtIn, b_in, qkvp, 384, 1);
    // 3. gated scores: e = exp(leaky(Hp Hp^T) * A), rowsum += partials
    gated_tc<<<dim3(8, 16, 8), 256, sizeof(GatedSmem)>>>(Hp, A, attnp, rowsump);
    // 4. tensor-core fused MHA split-K -> unnormalized partials
    mha_tc<<<dim3(32, 8, 2), 256, sizeof(MhaSmem)>>>(
        qkvp, attnp, rowsump, oAp, oBp, lAp, lBp);
    // 5. combine partials -> o (rounded)
    combine_kernel<<<B_ * N_ * E_ / (4 * 256), 256>>>(oAp, oBp, lAp, lBp, op);
    // 6. o2 = round(o @ W_out + b_out)
    gemm_tc<<<dim3(128, 2), 256>>>(op, wtOut, b_out, o2p, 128, 1);
    // 7. out = o2 @ W_fin + b_fin   (final: no rounding)
    gemm_tc<<<dim3(128, 2), 256>>>(o2p, wtFin, b_fin, out, 128, 0);
}

// round 17
// speedup vs baseline: 1.4304x; 1.0883x over previous
#include <cuda_runtime.h>
#include <math.h>
#include <stdint.h>

// Problem constants
#define B_ 8
#define N_ 1024
#define E_ 128

// ---------------- helpers ---------------------------------------------------
__device__ __forceinline__ uint32_t saddr(const void* p) {
    return (uint32_t)__cvta_generic_to_shared(p);
}
__device__ __forceinline__ float f2tf32(float x) {
    uint32_t r; asm("cvt.rna.tf32.f32 %0, %1;" : "=r"(r) : "f"(x));
    return __uint_as_float(r);
}
__device__ __forceinline__ float ex2(float x) {
    float r; asm("ex2.approx.ftz.f32 %0, %1;" : "=f"(r) : "f"(x));
    return r;
}
__device__ __forceinline__ void mma_tf32(float* d, const uint32_t* a,
                                         const uint32_t* b) {
    asm volatile(
        "mma.sync.aligned.m16n8k8.row.col.f32.tf32.tf32.f32 "
        "{%0,%1,%2,%3}, {%4,%5,%6,%7}, {%8,%9}, {%0,%1,%2,%3};\n"
        : "+f"(d[0]), "+f"(d[1]), "+f"(d[2]), "+f"(d[3])
        : "r"(a[0]), "r"(a[1]), "r"(a[2]), "r"(a[3]), "r"(b[0]), "r"(b[1]));
}
__device__ __forceinline__ void cpa16(uint32_t dst, const void* src) {
    asm volatile("cp.async.cg.shared.global [%0], [%1], 16;"
                 :: "r"(dst), "l"(src));
}
__device__ __forceinline__ void cp_commit() {
    asm volatile("cp.async.commit_group;");
}
__device__ __forceinline__ void cp_wait1() {
    asm volatile("cp.async.wait_group 1;");
}
__device__ __forceinline__ void cp_wait0() {
    asm volatile("cp.async.wait_group 0;");
}
// C-frag (c0,c1 at cols 2t,2t+1) -> A-frag (col t) relayout + rna cvt
__device__ __forceinline__ uint32_t relay(float c0, float c1, int src, bool odd) {
    float x = __shfl_sync(0xffffffffu, c0, src);
    float y = __shfl_sync(0xffffffffu, c1, src);
    uint32_t r;
    asm("cvt.rna.tf32.f32 %0, %1;" : "=r"(r) : "f"(odd ? y : x));
    return r;
}

#define LOG2E 1.4426950408889634f

// ---------------- scratch (static device globals; no allocation) ----------
__device__ float g_Hr[B_ * N_ * E_];            // rounded H
__device__ float g_Hp[B_ * N_ * E_];            // rounded Hp
__device__ float g_qkv[B_ * N_ * 3 * E_];       // rounded qkv
__device__ float g_attn[(size_t)B_ * N_ * N_];  // unnormalized exp
__device__ float g_rowsum[B_ * N_];
__device__ float g_oA[B_ * N_ * E_];            // split-K partials
__device__ float g_oB[B_ * N_ * E_];
__device__ float g_lA[B_ * N_ * 8];
__device__ float g_lB[B_ * N_ * 8];
__device__ float g_o2[B_ * N_ * E_];            // out-proj out (rounded)
// transposed + rounded weights: Wt[c][k] = tf32(W[k][c])
__device__ float g_WtLin[E_ * E_];
__device__ float g_WtIn[3 * E_ * E_];
__device__ float g_WtOut[E_ * E_];
__device__ float g_WtFin[E_ * E_];

// ---------------------------------------------------------------------------
// Single consolidated prep launch (see block ranges inline)
// ---------------------------------------------------------------------------
__global__ __launch_bounds__(256) void prep_all(
    const float* __restrict__ H,
    const float* __restrict__ W_lin, const float* __restrict__ W_in,
    const float* __restrict__ W_out, const float* __restrict__ W_fin,
    float* __restrict__ Hr,
    float* __restrict__ wtLin, float* __restrict__ wtIn,
    float* __restrict__ wtOut, float* __restrict__ wtFin,
    float* __restrict__ rowsum)
{
    int bid = blockIdx.x;
    int t   = threadIdx.x;
    if (bid < 1024) {
        int i = bid * 256 + t;
        float4 v = ((const float4*)H)[i];
        v.x = f2tf32(v.x); v.y = f2tf32(v.y);
        v.z = f2tf32(v.z); v.w = f2tf32(v.w);
        ((float4*)Hr)[i] = v;
    } else if (bid < 1088) {
        int idx = (bid - 1024) * 256 + t;
        int k = idx >> 7, c = idx & 127;
        wtLin[c * 128 + k] = f2tf32(W_lin[idx]);
    } else if (bid < 1280) {
        int idx = (bid - 1088) * 256 + t;
        int k = idx / 384, c = idx % 384;
        wtIn[c * 128 + k] = f2tf32(W_in[idx]);
    } else if (bid < 1344) {
        int idx = (bid - 1280) * 256 + t;
        int k = idx >> 7, c = idx & 127;
        wtOut[c * 128 + k] = f2tf32(W_out[idx]);
    } else if (bid < 1408) {
        int idx = (bid - 1344) * 256 + t;
        int k = idx >> 7, c = idx & 127;
        wtFin[c * 128 + k] = f2tf32(W_fin[idx]);
    } else {
        int i = (bid - 1408) * 256 + t;
        ((float4*)rowsum)[i] = make_float4(0.f, 0.f, 0.f, 0.f);
    }
}

// ---------------------------------------------------------------------------
// Tensor-core GEMM + bias (cp.async double-buffered, BM=64 BN=64)
// ---------------------------------------------------------------------------
struct GemmSmem {
    float As[2][64][36];
    float Bs[2][64][36];
};

__device__ __forceinline__ void gemm_issue(
    GemmSmem& S, int bi, const float* A, const float* Wt,
    int row0, int col0, int k0, int t)
{
    #pragma unroll
    for (int i = 0; i < 2; i++) {
        int idx = t + i * 256;
        int r = idx >> 3, kk = (idx & 7) << 2;
        cpa16(saddr(&S.As[bi][r][kk]), &A[(size_t)(row0 + r) * 128 + k0 + kk]);
        cpa16(saddr(&S.Bs[bi][r][kk]), &Wt[(size_t)(col0 + r) * 128 + k0 + kk]);
    }
}

__global__ __launch_bounds__(256, 3) void gemm_tc(
    const float* __restrict__ A, const float* __restrict__ Wt,
    const float* __restrict__ bias, float* __restrict__ C,
    int NC, int round_out)
{
    __shared__ GemmSmem S;

    int row0 = blockIdx.x * 64;
    int col0 = blockIdx.y * 64;
    int t    = threadIdx.x;
    int w    = t >> 5;
    int lane = t & 31;
    int g    = lane >> 2;
    int tig  = lane & 3;
    int wm   = (w & 1) * 32;
    int wn   = (w >> 1) * 16;

    gemm_issue(S, 0, A, Wt, row0, col0, 0, t);  cp_commit();
    gemm_issue(S, 1, A, Wt, row0, col0, 32, t); cp_commit();

    float acc[2][2][4] = {};

    #pragma unroll 1
    for (int c = 0; c < 4; c++) {
        int bi = c & 1;
        if (c < 3) cp_wait1(); else cp_wait0();
        __syncthreads();

        #pragma unroll
        for (int s = 0; s < 4; s++) {
            uint32_t af[2][4], bf[2][2];
            #pragma unroll
            for (int mt = 0; mt < 2; mt++) {
                const float* base = &S.As[bi][wm + 16 * mt + g][8 * s + tig];
                af[mt][0] = __float_as_uint(base[0]);
                af[mt][1] = __float_as_uint(base[8 * 36]);
                af[mt][2] = __float_as_uint(base[4]);
                af[mt][3] = __float_as_uint(base[8 * 36 + 4]);
            }
            #pragma unroll
            for (int nt = 0; nt < 2; nt++) {
                const float* base = &S.Bs[bi][wn + 8 * nt + g][8 * s + tig];
                bf[nt][0] = __float_as_uint(base[0]);
                bf[nt][1] = __float_as_uint(base[4]);
            }
            #pragma unroll
            for (int mt = 0; mt < 2; mt++)
                #pragma unroll
                for (int nt = 0; nt < 2; nt++)
                    mma_tf32(acc[mt][nt], af[mt], bf[nt]);
        }

        __syncthreads();
        if (c + 2 < 4) {
            gemm_issue(S, bi, A, Wt, row0, col0, (c + 2) * 32, t);
            cp_commit();
        }
    }

    #pragma unroll
    for (int mt = 0; mt < 2; mt++) {
        #pragma unroll
        for (int eh = 0; eh < 2; eh++) {
            int row = row0 + wm + 16 * mt + 8 * eh + g;
            #pragma unroll
            for (int nt = 0; nt < 2; nt++) {
                int col = col0 + wn + 8 * nt + 2 * tig;
                float2 bv = *(const float2*)&bias[col];
                float v0 = acc[mt][nt][2 * eh]     + bv.x;
                float v1 = acc[mt][nt][2 * eh + 1] + bv.y;
                if (round_out) { v0 = f2tf32(v0); v1 = f2tf32(v1); }
                *(float2*)&C[(size_t)row * NC + col] = make_float2(v0, v1);
            }
        }
    }
}

// ---------------------------------------------------------------------------
// Fused combine + GEMM:  C = round((OA+OB)/(LA+LB)) @ Wt + bias
// Full-tile staging: A computed via LDG + combine math; B via cp.async.
// NC = 128. grid = (M/64, 2).
// ---------------------------------------------------------------------------
struct GemmCombSmem {
    float As[64][132];
    float Bs[64][132];
};

__global__ __launch_bounds__(256, 3) void gemm_comb_tc(
    const float* __restrict__ OA, const float* __restrict__ OB,
    const float* __restrict__ LA, const float* __restrict__ LB,
    const float* __restrict__ Wt, const float* __restrict__ bias,
    float* __restrict__ C, int round_out)
{
    extern __shared__ char gc_raw[];
    GemmCombSmem& S = *reinterpret_cast<GemmCombSmem*>(gc_raw);

    int row0 = blockIdx.x * 64;
    int col0 = blockIdx.y * 64;
    int t    = threadIdx.x;
    int w    = t >> 5;
    int lane = t & 31;
    int g    = lane >> 2;
    int tig  = lane & 3;
    int wm   = (w & 1) * 32;
    int wn   = (w >> 1) * 16;

    // stage B (full 64x128) via cp.async
    #pragma unroll
    for (int i = 0; i < 8; i++) {
        int idx = t + i * 256;              // 2048 float4
        int r = idx >> 5, c = (idx & 31) << 2;
        cpa16(saddr(&S.Bs[r][c]), &Wt[(size_t)(col0 + r) * 128 + c]);
    }
    cp_commit();

    // stage A: combine partials, normalize, round
    #pragma unroll
    for (int i = 0; i < 8; i++) {
        int idx = t + i * 256;
        int r = idx >> 5, c = (idx & 31) << 2;
        int row = row0 + r;
        int hh  = c >> 4;
        float inv = 1.0f / (LA[(size_t)row * 8 + hh] + LB[(size_t)row * 8 + hh]);
        float4 a = *(const float4*)&OA[(size_t)row * 128 + c];
        float4 b = *(const float4*)&OB[(size_t)row * 128 + c];
        float4 v;
        v.x = f2tf32((a.x + b.x) * inv); v.y = f2tf32((a.y + b.y) * inv);
        v.z = f2tf32((a.z + b.z) * inv); v.w = f2tf32((a.w + b.w) * inv);
        *(float4*)&S.As[r][c] = v;
    }
    cp_wait0();
    __syncthreads();

    float acc[2][2][4] = {};
    #pragma unroll 4
    for (int s = 0; s < 16; s++) {
        uint32_t af[2][4], bf[2][2];
        #pragma unroll
        for (int mt = 0; mt < 2; mt++) {
            const float* base = &S.As[wm + 16 * mt + g][8 * s + tig];
            af[mt][0] = __float_as_uint(base[0]);
            af[mt][1] = __float_as_uint(base[8 * 132]);
            af[mt][2] = __float_as_uint(base[4]);
            af[mt][3] = __float_as_uint(base[8 * 132 + 4]);
        }
        #pragma unroll
        for (int nt = 0; nt < 2; nt++) {
            const float* base = &S.Bs[wn + 8 * nt + g][8 * s + tig];
            bf[nt][0] = __float_as_uint(base[0]);
            bf[nt][1] = __float_as_uint(base[4]);
        }
        #pragma unroll
        for (int mt = 0; mt < 2; mt++)
            #pragma unroll
            for (int nt = 0; nt < 2; nt++)
                mma_tf32(acc[mt][nt], af[mt], bf[nt]);
    }

    #pragma unroll
    for (int mt = 0; mt < 2; mt++) {
        #pragma unroll
        for (int eh = 0; eh < 2; eh++) {
            int row = row0 + wm + 16 * mt + 8 * eh + g;
            #pragma unroll
            for (int nt = 0; nt < 2; nt++) {
                int col = col0 + wn + 8 * nt + 2 * tig;
                float2 bv = *(const float2*)&bias[col];
                float v0 = acc[mt][nt][2 * eh]     + bv.x;
                float v1 = acc[mt][nt][2 * eh + 1] + bv.y;
                if (round_out) { v0 = f2tf32(v0); v1 = f2tf32(v1); }
                *(float2*)&C[(size_t)row * 128 + col] = make_float2(v0, v1);
            }
        }
    }
}

// ---------------------------------------------------------------------------
// Tensor-core gated scores + fused exp + row-sum, cp.async double-buffered.
// ---------------------------------------------------------------------------
struct GatedSmem {
    float Ns[2][128][36];
    float Ms[2][64][36];
};

__device__ __forceinline__ void gated_issue(
    GatedSmem& S, int bi, const float* Hb, int n0, int m0, int k0, int t)
{
    #pragma unroll
    for (int i = 0; i < 4; i++) {
        int idx = t + i * 256;
        int r = idx >> 3, kk = (idx & 7) << 2;
        cpa16(saddr(&S.Ns[bi][r][kk]), &Hb[(size_t)(n0 + r) * 128 + k0 + kk]);
    }
    #pragma unroll
    for (int i = 0; i < 2; i++) {
        int idx = t + i * 256;
        int r = idx >> 3, kk = (idx & 7) << 2;
        cpa16(saddr(&S.Ms[bi][r][kk]), &Hb[(size_t)(m0 + r) * 128 + k0 + kk]);
    }
}

__global__ __launch_bounds__(256, 3) void gated_tc(
    const float* __restrict__ Hpr, const float* __restrict__ Adj,
    float* __restrict__ out, float* __restrict__ rowsum)
{
    extern __shared__ char gs_raw[];
    GatedSmem& S = *reinterpret_cast<GatedSmem*>(gs_raw);

    int b  = blockIdx.z;
    int n0 = blockIdx.x * 128;
    int m0 = blockIdx.y * 64;
    const float* Hb = Hpr + (size_t)b * N_ * E_;

    int t    = threadIdx.x;
    int w    = t >> 5;
    int lane = t & 31;
    int g    = lane >> 2;
    int tig  = lane & 3;
    int wn   = (w & 1) * 64;
    int wm   = (w >> 1) * 16;

    gated_issue(S, 0, Hb, n0, m0, 0, t);  cp_commit();
    gated_issue(S, 1, Hb, n0, m0, 32, t); cp_commit();

    float acc[4][2][4] = {};

    #pragma unroll 1
    for (int c = 0; c < 4; c++) {
        int bi = c & 1;
        if (c < 3) cp_wait1(); else cp_wait0();
        __syncthreads();

        #pragma unroll
        for (int s = 0; s < 4; s++) {
            uint32_t af[4][4], bf[2][2];
            #pragma unroll
            for (int mt = 0; mt < 4; mt++) {
                const float* base = &S.Ns[bi][wn + 16 * mt + g][8 * s + tig];
                af[mt][0] = __float_as_uint(base[0]);
                af[mt][1] = __float_as_uint(base[8 * 36]);
                af[mt][2] = __float_as_uint(base[4]);
                af[mt][3] = __float_as_uint(base[8 * 36 + 4]);
            }
            #pragma unroll
            for (int nt = 0; nt < 2; nt++) {
                const float* base = &S.Ms[bi][wm + 8 * nt + g][8 * s + tig];
                bf[nt][0] = __float_as_uint(base[0]);
                bf[nt][1] = __float_as_uint(base[4]);
            }
            #pragma unroll
            for (int mt = 0; mt < 4; mt++)
                #pragma unroll
                for (int nt = 0; nt < 2; nt++)
                    mma_tf32(acc[mt][nt], af[mt], bf[nt]);
        }

        __syncthreads();
        if (c + 2 < 4) {
            gated_issue(S, bi, Hb, n0, m0, (c + 2) * 32, t);
            cp_commit();
        }
    }

    #pragma unroll
    for (int mt = 0; mt < 4; mt++) {
        #pragma unroll
        for (int eh = 0; eh < 2; eh++) {
            int n = n0 + wn + 16 * mt + g + eh * 8;
            float partial = 0.f;
            #pragma unroll
            for (int nt = 0; nt < 2; nt++) {
                int m = m0 + wm + 8 * nt + 2 * tig;
                size_t addr = ((size_t)b * N_ + n) * N_ + m;
                float2 adj = *(const float2*)&Adj[addr];
                float v0 = acc[mt][nt][2 * eh];
                float v1 = acc[mt][nt][2 * eh + 1];
                v0 = (v0 >= 0.f) ? v0 : 0.2f * v0;
                v1 = (v1 >= 0.f) ? v1 : 0.2f * v1;
                float e0 = ex2(v0 * adj.x * LOG2E);
                float e1 = ex2(v1 * adj.y * LOG2E);
                partial += e0 + e1;
                *(float2*)&out[addr] = make_float2(e0, e1);
            }
            partial += __shfl_xor_sync(0xffffffffu, partial, 1);
            partial += __shfl_xor_sync(0xffffffffu, partial, 2);
            if (tig == 0)
                atomicAdd(&rowsum[(size_t)b * N_ + n], partial);
        }
    }
}

// ---------------------------------------------------------------------------
// Tensor-core fused MHA, split-K(2), shuffle P-relayout.
// K buffer XOR-swizzled (no pad) to cut smem below the 3-block/SM threshold.
// Block = 32 queries x 8 heads (warp = head); grid = (N/32, B, 2).
// ---------------------------------------------------------------------------
struct MhaSmem {
    float Ks[2][32][128];   // XOR-swizzled: col group' = group ^ (row & 7)
    float Vs[2][32][132];   // padded, conflict-free
    float Wm[2][32][36];
};

__device__ __forceinline__ void mha_issue(
    MhaSmem& S, int bi, const float* kvbase, const float* mbase,
    int m0, int t)
{
    int srow = t >> 3;
    int sc16 = (t & 7) * 16;
    int mc4  = (t & 7) * 4;
    int sw   = srow & 7;
    const float* kr = kvbase + (size_t)(m0 + srow) * 384 + 128 + sc16;
    uint32_t kd = saddr(&S.Ks[bi][srow][0]);
    uint32_t vd = saddr(&S.Vs[bi][srow][sc16]);
    #pragma unroll
    for (int c = 0; c < 16; c += 4) {
        int grp = (sc16 + c) >> 2;
        cpa16(kd + (((grp ^ sw) << 2) * 4), kr + c);
        cpa16(vd + c * 4, kr + 128 + c);
    }
    cpa16(saddr(&S.Wm[bi][srow][mc4]),
          mbase + (size_t)srow * N_ + m0 + mc4);
}

__global__ void __launch_bounds__(256, 3) mha_tc(
    const float* __restrict__ qkv, const float* __restrict__ attn,
    const float* __restrict__ rowsum,
    float* __restrict__ OA, float* __restrict__ OB,
    float* __restrict__ LA, float* __restrict__ LB)
{
    extern __shared__ char smem_raw[];
    MhaSmem& S = *reinterpret_cast<MhaSmem*>(smem_raw);

    int b    = blockIdx.y;
    int n0   = blockIdx.x * 32;
    int msta = blockIdx.z * 512;
    int t    = threadIdx.x;
    int h    = t >> 5;
    int lane = t & 31;
    int g    = lane >> 2;
    int tig  = lane & 3;
    int src0 = (lane & 28) | (tig >> 1);
    int src1 = src0 + 2;
    bool odd = tig & 1;

    float* Op = blockIdx.z ? OB : OA;
    float* Lp = blockIdx.z ? LB : LA;

    const float* kvbase = qkv + (size_t)b * N_ * 384;
    const float* mbase  = attn + ((size_t)b * N_ + n0) * N_;

    mha_issue(S, 0, kvbase, mbase, msta, t);      cp_commit();
    mha_issue(S, 1, kvbase, mbase, msta + 32, t); cp_commit();

    // exp2-folded 1/rowsum
    const float* rsb = rowsum + (size_t)b * N_ + n0;
    float is0 = LOG2E / rsb[g];
    float is1 = LOG2E / rsb[g + 8];
    float is2 = LOG2E / rsb[g + 16];
    float is3 = LOG2E / rsb[g + 24];

    // Q fragments, scaled by 0.25 * log2(e)
    uint32_t qf[2][2][4];
    {
        const float qs = 0.25f * LOG2E;
        const float* qbase = qkv + ((size_t)b * N_ + n0) * 384 + h * 16;
        #pragma unroll
        for (int i = 0; i < 2; i++)
            #pragma unroll
            for (int s = 0; s < 2; s++) {
                const float* p0 = qbase + (size_t)(16 * i + g) * 384 + 8 * s + tig;
                const float* p1 = p0 + 8 * 384;
                qf[i][s][0] = __float_as_uint(f2tf32(p0[0] * qs));
                qf[i][s][1] = __float_as_uint(f2tf32(p1[0] * qs));
                qf[i][s][2] = __float_as_uint(f2tf32(p0[4] * qs));
                qf[i][s][3] = __float_as_uint(f2tf32(p1[4] * qs));
            }
    }

    float oacc[2][2][4] = {};
    float lsum[4] = {0.f, 0.f, 0.f, 0.f};

    #pragma unroll 1
    for (int tile = 0; tile < 16; tile++) {
        int bi = tile & 1;
        if (tile < 15) cp_wait1(); else cp_wait0();
        __syncthreads();

        #pragma unroll
        for (int j = 0; j < 4; j++) {
            float sacc0[4] = {0.f, 0.f, 0.f, 0.f};
            float sacc1[4] = {0.f, 0.f, 0.f, 0.f};
            #pragma unroll
            for (int s = 0; s < 2; s++) {
                int grp = 4 * h + 2 * s;
                uint32_t bf[2];
                bf[0] = __float_as_uint(
                    S.Ks[bi][8 * j + g][((grp ^ g) << 2) + tig]);
                bf[1] = __float_as_uint(
                    S.Ks[bi][8 * j + g][(((grp + 1) ^ g) << 2) + tig]);
                mma_tf32(sacc0, qf[0][s], bf);
                mma_tf32(sacc1, qf[1][s], bf);
            }

            int c = 8 * j + 2 * tig;
            float2 w00 = *(const float2*)&S.Wm[bi][g][c];
            float2 w01 = *(const float2*)&S.Wm[bi][g + 8][c];
            float2 w10 = *(const float2*)&S.Wm[bi][g + 16][c];
            float2 w11 = *(const float2*)&S.Wm[bi][g + 24][c];
            float p00 = ex2(fmaf(w00.x, is0, sacc0[0]));
            float p01 = ex2(fmaf(w00.y, is0, sacc0[1]));
            float p02 = ex2(fmaf(w01.x, is1, sacc0[2]));
            float p03 = ex2(fmaf(w01.y, is1, sacc0[3]));
            float p10 = ex2(fmaf(w10.x, is2, sacc1[0]));
            float p11 = ex2(fmaf(w10.y, is2, sacc1[1]));
            float p12 = ex2(fmaf(w11.x, is3, sacc1[2]));
            float p13 = ex2(fmaf(w11.y, is3, sacc1[3]));
            lsum[0] += p00 + p01;
            lsum[1] += p02 + p03;
            lsum[2] += p10 + p11;
            lsum[3] += p12 + p13;

            uint32_t af0[4], af1[4];
            af0[0] = relay(p00, p01, src0, odd);
            af0[1] = relay(p02, p03, src0, odd);
            af0[2] = relay(p00, p01, src1, odd);
            af0[3] = relay(p02, p03, src1, odd);
            af1[0] = relay(p10, p11, src0, odd);
            af1[1] = relay(p12, p13, src0, odd);
            af1[2] = relay(p10, p11, src1, odd);
            af1[3] = relay(p12, p13, src1, odd);

            uint32_t bv0[2], bv1[2];
            bv0[0] = __float_as_uint(S.Vs[bi][8 * j + tig][h * 16 + g]);
            bv0[1] = __float_as_uint(S.Vs[bi][8 * j + tig + 4][h * 16 + g]);
            bv1[0] = __float_as_uint(S.Vs[bi][8 * j + tig][h * 16 + 8 + g]);
            bv1[1] = __float_as_uint(S.Vs[bi][8 * j + tig + 4][h * 16 + 8 + g]);
            mma_tf32(oacc[0][0], af0, bv0);
            mma_tf32(oacc[0][1], af0, bv1);
            mma_tf32(oacc[1][0], af1, bv0);
            mma_tf32(oacc[1][1], af1, bv1);
        }

        __syncthreads();
        if (tile + 2 < 16) {
            mha_issue(S, bi, kvbase, mbase, msta + (tile + 2) * 32, t);
            cp_commit();
        }
    }

    #pragma unroll
    for (int k = 0; k < 4; k++) {
        lsum[k] += __shfl_xor_sync(0xffffffffu, lsum[k], 1);
        lsum[k] += __shfl_xor_sync(0xffffffffu, lsum[k], 2);
    }
    #pragma unroll
    for (int i = 0; i < 2; i++) {
        #pragma unroll
        for (int jd = 0; jd < 2; jd++) {
            size_t base0 = ((size_t)b * N_ + n0 + 16 * i + g) * 128
                           + h * 16 + 8 * jd + 2 * tig;
            size_t base1 = base0 + (size_t)8 * 128;
            *(float2*)&Op[base0] = make_float2(oacc[i][jd][0], oacc[i][jd][1]);
            *(float2*)&Op[base1] = make_float2(oacc[i][jd][2], oacc[i][jd][3]);
        }
    }
    if (tig == 0) {
        Lp[((size_t)(b * N_ + n0 + g)) * 8 + h]      = lsum[0];
        Lp[((size_t)(b * N_ + n0 + 8 + g)) * 8 + h]  = lsum[1];
        Lp[((size_t)(b * N_ + n0 + 16 + g)) * 8 + h] = lsum[2];
        Lp[((size_t)(b * N_ + n0 + 24 + g)) * 8 + h] = lsum[3];
    }
}

// ---------------------------------------------------------------------------
extern "C" void kernel_launch(void* const* d_in, const int* in_sizes, int n_in,
                              void* d_out, int out_size)
{
    const float* H     = (const float*)d_in[0];
    const float* A     = (const float*)d_in[1];
    const float* W_lin = (const float*)d_in[2];
    const float* b_lin = (const float*)d_in[3];
    const float* W_in  = (const float*)d_in[4];
    const float* b_in  = (const float*)d_in[5];
    const float* W_out = (const float*)d_in[6];
    const float* b_out = (const float*)d_in[7];
    const float* W_fin = (const float*)d_in[8];
    const float* b_fin = (const float*)d_in[9];
    float* out = (float*)d_out;

    float *Hr, *Hp, *qkvp, *attnp, *rowsump, *oAp, *oBp, *lAp, *lBp, *o2p;
    float *wtLin, *wtIn, *wtOut, *wtFin;
    cudaGetSymbolAddress((void**)&Hr,      g_Hr);
    cudaGetSymbolAddress((void**)&Hp,      g_Hp);
    cudaGetSymbolAddress((void**)&qkvp,    g_qkv);
    cudaGetSymbolAddress((void**)&attnp,   g_attn);
    cudaGetSymbolAddress((void**)&rowsump, g_rowsum);
    cudaGetSymbolAddress((void**)&oAp,     g_oA);
    cudaGetSymbolAddress((void**)&oBp,     g_oB);
    cudaGetSymbolAddress((void**)&lAp,     g_lA);
    cudaGetSymbolAddress((void**)&lBp,     g_lB);
    cudaGetSymbolAddress((void**)&o2p,     g_o2);
    cudaGetSymbolAddress((void**)&wtLin,   g_WtLin);
    cudaGetSymbolAddress((void**)&wtIn,    g_WtIn);
    cudaGetSymbolAddress((void**)&wtOut,   g_WtOut);
    cudaGetSymbolAddress((void**)&wtFin,   g_WtFin);

    static cudaStream_t s2 = nullptr;
    static cudaEvent_t evA = nullptr, evB = nullptr;
    static int init_done = 0;
    if (!init_done) {
        cudaFuncSetAttribute(mha_tc, cudaFuncAttributeMaxDynamicSharedMemorySize,
                             (int)sizeof(MhaSmem));
        cudaFuncSetAttribute(gated_tc, cudaFuncAttributeMaxDynamicSharedMemorySize,
                             (int)sizeof(GatedSmem));
        cudaFuncSetAttribute(gemm_comb_tc,
                             cudaFuncAttributeMaxDynamicSharedMemorySize,
                             (int)sizeof(GemmCombSmem));
        cudaStreamCreateWithFlags(&s2, cudaStreamNonBlocking);
        cudaEventCreateWithFlags(&evA, cudaEventDisableTiming);
        cudaEventCreateWithFlags(&evB, cudaEventDisableTiming);
        init_done = 1;
    }

    // 0. ONE prep launch: round H, transpose+round all weights, zero rowsum
    prep_all<<<1416, 256>>>(H, W_lin, W_in, W_out, W_fin,
                            Hr, wtLin, wtIn, wtOut, wtFin, rowsump);

    // 1. Hp = round(Hr @ W_lin + b_lin)
    gemm_tc<<<dim3(128, 2), 256>>>(Hr, wtLin, b_lin, Hp, 128, 1);

    // fork: qkv GEMM on s2, concurrent with gated scores on default stream
    cudaEventRecord(evA, 0);
    cudaStreamWaitEvent(s2, evA, 0);
    // 2a. qkv = round(Hp @ W_in + b_in)          [stream s2]
    gemm_tc<<<dim3(128, 6), 256, 0, s2>>>(Hp, wtIn, b_in, qkvp, 384, 1);
    // 2b. gated scores + rowsum                  [default stream]
    gated_tc<<<dim3(8, 16, 8), 256, sizeof(GatedSmem)>>>(Hp, A, attnp, rowsump);
    // join
    cudaEventRecord(evB, s2);
    cudaStreamWaitEvent(0, evB, 0);

    // 3. tensor-core fused MHA split-K -> unnormalized partials
    mha_tc<<<dim3(32, 8, 2), 256, sizeof(MhaSmem)>>>(
        qkvp, attnp, rowsump, oAp, oBp, lAp, lBp);
    // 4. o2 = round( combine(OA,OB,L) @ W_out + b_out )   (fused combine)
    gemm_comb_tc<<<dim3(128, 2), 256, sizeof(GemmCombSmem)>>>(
        oAp, oBp, lAp, lBp, wtOut, b_out, o2p, 1);
    // 5. out = o2 @ W_fin + b_fin   (final: no rounding)
    gemm_tc<<<dim3(128, 2), 256>>>(o2p, wtFin, b_fin, out, 128, 0);
}